// round 8
// baseline (speedup 1.0000x reference)
#include <cuda_runtime.h>
#include <cuda_fp16.h>
#include <cstdint>
#include <cstddef>

#define NN  102400
#define EE  819200
#define DD  128
#define LL  5
#define TSG 1024
#define NCHUNK 400          // NN / 256

// ---------------- scratch (static device globals) ----------------------------
__device__ __half g_hh16[(size_t)NN * DD];       // fp16 activations (gather in)
__device__ __half g_agg16[(size_t)NN * DD];      // MLP input
__device__ __half g_w16t[(size_t)LL * 65536];    // transposed fp16 weights
__device__ int    g_rowptr[NN + 1];
__device__ int    g_cur[NN];
__device__ int    g_bsum[NCHUNK];
__device__ int    g_col[EE];
__device__ float  g_cnt[TSG];
__device__ int    g_off[64];

// ---------------- x -> fp16 (once) --------------------------------------------
__global__ void x2h_kernel(const float* __restrict__ x, int total4) {
    int i = blockIdx.x * blockDim.x + threadIdx.x;
    if (i >= total4) return;
    float4 v = ((const float4*)x)[i];
    __half2 h0 = __floats2half2_rn(v.x, v.y);
    __half2 h1 = __floats2half2_rn(v.z, v.w);
    uint2 o = {*(uint32_t*)&h0, *(uint32_t*)&h1};
    ((uint2*)g_hh16)[i] = o;
}

// ---------------- weight convert + transpose ---------------------------------
// per layer l: [0,32768): W1^T [n=256][k=128]; [32768,65536): W2^T [n=128][k=256]
__global__ void convw_kernel(const float* __restrict__ W1,
                             const float* __restrict__ W2) {
    int i = blockIdx.x * blockDim.x + threadIdx.x;
    if (i >= LL * 65536) return;
    int l = i >> 16, r = i & 65535;
    float v;
    if (r < 32768) {
        int n = r >> 7, k = r & 127;
        v = W1[(size_t)l * 32768 + k * 256 + n];
    } else {
        int r2 = r - 32768;
        int n = r2 >> 8, k = r2 & 255;
        v = W2[(size_t)l * 32768 + k * 128 + n];
    }
    g_w16t[i] = __float2half_rn(v);
}

// ---------------- CSR build ---------------------------------------------------
__global__ void hist_kernel(const int* __restrict__ dst, int E) {
    int e = blockIdx.x * blockDim.x + threadIdx.x;
    if (e < E) atomicAdd(&g_cur[dst[e]], 1);
}

__global__ void scan1_kernel() {
    __shared__ int s[256];
    int t = threadIdx.x, i = blockIdx.x * 256 + t;
    int v = g_cur[i];
    s[t] = v;
    __syncthreads();
#pragma unroll
    for (int o = 1; o < 256; o <<= 1) {
        int u = (t >= o) ? s[t - o] : 0;
        __syncthreads();
        s[t] += u;
        __syncthreads();
    }
    g_rowptr[i] = s[t] - v;
    if (t == 255) g_bsum[blockIdx.x] = s[255];
}

__global__ void scan2_kernel() {
    __shared__ int s[512];
    int t = threadIdx.x;
    int v = (t < NCHUNK) ? g_bsum[t] : 0;
    s[t] = v;
    __syncthreads();
#pragma unroll
    for (int o = 1; o < 512; o <<= 1) {
        int u = (t >= o) ? s[t - o] : 0;
        __syncthreads();
        s[t] += u;
        __syncthreads();
    }
    if (t < NCHUNK) g_bsum[t] = s[t] - v;
}

__global__ void scan3_kernel(int E) {
    int i = blockIdx.x * blockDim.x + threadIdx.x;
    if (i < NN) g_rowptr[i] += g_bsum[i >> 8];
    if (i == 0) g_rowptr[NN] = E;
}

__global__ void fill_kernel(const int* __restrict__ src,
                            const int* __restrict__ dst, int E) {
    int e = blockIdx.x * blockDim.x + threadIdx.x;
    if (e >= E) return;
    int d = dst[e];
    int p = g_rowptr[d] + atomicAdd(&g_cur[d], 1);
    g_col[p] = src[e];
}

// ---------------- gather: agg16[d] = fp16((1+eps)h[d] + sum h[nb]) ------------
__device__ __forceinline__ void acc4(float* acc, uint2 v) {
    float2 f0 = __half22float2(*(const __half2*)&v.x);
    float2 f1 = __half22float2(*(const __half2*)&v.y);
    acc[0] += f0.x; acc[1] += f0.y; acc[2] += f1.x; acc[3] += f1.y;
}

__global__ void gather_kernel(const float* __restrict__ eps, int l, int Nn) {
    long long tid = (long long)blockIdx.x * blockDim.x + threadIdx.x;
    int node = (int)(tid >> 5);
    if (node >= Nn) return;
    int lane = (int)(tid & 31);
    float e1 = 1.0f + eps[l];
    const uint2* hv = (const uint2*)g_hh16;

    // self * (1+eps)
    float acc[4];
    {
        uint2 v = hv[(size_t)node * 32 + lane];
        float2 f0 = __half22float2(*(const __half2*)&v.x);
        float2 f1 = __half22float2(*(const __half2*)&v.y);
        acc[0] = e1 * f0.x; acc[1] = e1 * f0.y;
        acc[2] = e1 * f1.x; acc[3] = e1 * f1.y;
    }

    int i = g_rowptr[node], t = g_rowptr[node + 1];
    for (; i + 4 <= t; i += 4) {
        int n0 = g_col[i], n1 = g_col[i + 1];
        int n2 = g_col[i + 2], n3 = g_col[i + 3];
        uint2 v0 = hv[(size_t)n0 * 32 + lane];
        uint2 v1 = hv[(size_t)n1 * 32 + lane];
        uint2 v2 = hv[(size_t)n2 * 32 + lane];
        uint2 v3 = hv[(size_t)n3 * 32 + lane];
        acc4(acc, v0); acc4(acc, v1); acc4(acc, v2); acc4(acc, v3);
    }
    for (; i < t; i++) acc4(acc, hv[(size_t)g_col[i] * 32 + lane]);

    __half2 h0 = __floats2half2_rn(acc[0], acc[1]);
    __half2 h1 = __floats2half2_rn(acc[2], acc[3]);
    uint2 o = {*(uint32_t*)&h0, *(uint32_t*)&h1};
    ((uint2*)(g_agg16 + (size_t)node * DD))[lane] = o;
}

// ---------------- persistent fused MLP ----------------------------------------
// grid = 148 persistent CTAs; each strides tiles of 128 rows.
// SMEM: W1 (stride 272, 69632B) | W2 (stride 528, 67584B) | AY (67584B)
#define CP16(smb, g) \
    asm volatile("cp.async.cg.shared.global [%0], [%1], 16;" :: "r"(smb), "l"(g))
#define W1O 0
#define W2O 69632
#define AYO 137216
#define SMEM_TOT 204800

__device__ __forceinline__ void red_add_v2(float* p, float2 v) {
    asm volatile("red.global.add.v2.f32 [%0], {%1,%2};"
                 :: "l"(p), "f"(v.x), "f"(v.y) : "memory");
}

__global__ __launch_bounds__(256) void mlp_fused(
    const __half* __restrict__ A, const __half* __restrict__ W1t,
    const float* __restrict__ b1, const __half* __restrict__ W2t,
    const float* __restrict__ b2, __half* __restrict__ H16,
    const int* __restrict__ batch, const int* __restrict__ sgb,
    float* __restrict__ out, int ntiles, int doRelu2, int doPool) {
    extern __shared__ char sm[];
    uint32_t sb  = (uint32_t)__cvta_generic_to_shared(sm);
    uint32_t w1b = sb + W1O, w2b = sb + W2O, ayb = sb + AYO;

    int tid  = threadIdx.x;
    int lane = tid & 31;
    int wid  = tid >> 5;
    int wm   = wid & 1;                      // 2 warp rows of 64
    int wn   = wid >> 1;                     // 4 warp cols
    int stride = gridDim.x;

    // ---- group 0: W1 + A(tile0); group 1: W2 ----
    for (int i = tid; i < 4096; i += 256) {  // W1: 256 rows x 16 chunks
        int r = i >> 4, c = i & 15;
        CP16(w1b + r * 272 + c * 16, W1t + (size_t)r * 128 + c * 8);
    }
    {
        int row0 = blockIdx.x * 128;
        for (int i = tid; i < 2048; i += 256) {  // A: 128 rows x 16 chunks
            int r = i >> 4, c = i & 15;
            CP16(ayb + r * 272 + c * 16, A + (size_t)(row0 + r) * 128 + c * 8);
        }
    }
    asm volatile("cp.async.commit_group;");
    for (int i = tid; i < 4096; i += 256) {  // W2: 128 rows x 32 chunks
        int r = i >> 5, c = i & 31;
        CP16(w2b + r * 528 + c * 16, W2t + (size_t)r * 256 + c * 8);
    }
    asm volatile("cp.async.commit_group;");
    asm volatile("cp.async.wait_group 1;");
    __syncthreads();

    int r8  = lane & 7;
    int sel = lane >> 3;
    int ll  = lane & 15;
    int bs  = ll >> 3;
    int br  = ll & 7;
    int g   = lane >> 2;
    int tg  = lane & 3;

    bool firstIter = true;
    for (int tile = blockIdx.x; tile < ntiles; tile += stride) {
        int row0 = tile * 128;
        int nextTile = tile + stride;
        bool hasNext = nextTile < ntiles;

        // ---- prefetch next A tile into registers (consumed post-GEMM2) ----
        uint4 pf[8];
        if (hasNext) {
            const uint4* Ag = (const uint4*)(A + (size_t)nextTile * 128 * 128);
#pragma unroll
            for (int j = 0; j < 8; j++) pf[j] = Ag[tid + 256 * j];
        }

        // ============ GEMM1: y[128,256] = A[128,128] @ W1 ============
        float acc[4][8][4];
#pragma unroll
        for (int mt = 0; mt < 4; mt++)
#pragma unroll
            for (int nt = 0; nt < 8; nt++)
#pragma unroll
                for (int j = 0; j < 4; j++) acc[mt][nt][j] = 0.0f;

#pragma unroll
        for (int k0 = 0; k0 < 4; k0++) {
#pragma unroll
            for (int ks = 0; ks < 2; ks++) {
                uint32_t a[4][4], b[8][2];
                int kb = k0 * 64 + ks * 32;
#pragma unroll
                for (int mt = 0; mt < 4; mt++) {
                    int m = wm * 64 + mt * 16 + (sel & 1) * 8 + r8;
                    uint32_t ad = ayb + m * 272 + kb + ((sel >> 1) & 1) * 16;
                    asm volatile(
                        "ldmatrix.sync.aligned.m8n8.x4.shared.b16 {%0,%1,%2,%3}, [%4];"
                        : "=r"(a[mt][0]), "=r"(a[mt][1]), "=r"(a[mt][2]), "=r"(a[mt][3])
                        : "r"(ad));
                }
#pragma unroll
                for (int nt = 0; nt < 8; nt++) {
                    int n = wn * 64 + nt * 8 + br;
                    uint32_t ad = w1b + n * 272 + kb + bs * 16;
                    asm volatile(
                        "ldmatrix.sync.aligned.m8n8.x2.shared.b16 {%0,%1}, [%2];"
                        : "=r"(b[nt][0]), "=r"(b[nt][1]) : "r"(ad));
                }
#pragma unroll
                for (int mt = 0; mt < 4; mt++)
#pragma unroll
                    for (int nt = 0; nt < 8; nt++) {
                        asm volatile(
                            "mma.sync.aligned.m16n8k16.row.col.f32.f16.f16.f32 "
                            "{%0,%1,%2,%3}, {%4,%5,%6,%7}, {%8,%9}, {%0,%1,%2,%3};"
                            : "+f"(acc[mt][nt][0]), "+f"(acc[mt][nt][1]),
                              "+f"(acc[mt][nt][2]), "+f"(acc[mt][nt][3])
                            : "r"(a[mt][0]), "r"(a[mt][1]), "r"(a[mt][2]), "r"(a[mt][3]),
                              "r"(b[nt][0]), "r"(b[nt][1]));
                    }
            }
        }
        __syncthreads();   // A reads done; AY becomes y

        // ---- bias + relu + fp16, store y to SMEM (stride 528) ----
#pragma unroll
        for (int mt = 0; mt < 4; mt++) {
#pragma unroll
            for (int nt = 0; nt < 8; nt++) {
                int col = wn * 64 + nt * 8 + tg * 2;
                float2 bv = *(const float2*)(b1 + col);
                int r0 = wm * 64 + mt * 16 + g;
                float f0 = fmaxf(acc[mt][nt][0] + bv.x, 0.0f);
                float f1 = fmaxf(acc[mt][nt][1] + bv.y, 0.0f);
                float f2 = fmaxf(acc[mt][nt][2] + bv.x, 0.0f);
                float f3 = fmaxf(acc[mt][nt][3] + bv.y, 0.0f);
                __half2 p0 = __floats2half2_rn(f0, f1);
                __half2 p1 = __floats2half2_rn(f2, f3);
                *(__half2*)(sm + AYO + r0 * 528 + col * 2)       = p0;
                *(__half2*)(sm + AYO + (r0 + 8) * 528 + col * 2) = p1;
            }
        }
        if (firstIter) {
            asm volatile("cp.async.wait_group 0;");   // W2 resident
            firstIter = false;
        }
        __syncthreads();

        // ============ GEMM2: h[128,128] = y[128,256] @ W2 ============
        float acc2[4][4][4];
#pragma unroll
        for (int mt = 0; mt < 4; mt++)
#pragma unroll
            for (int nt = 0; nt < 4; nt++)
#pragma unroll
                for (int j = 0; j < 4; j++) acc2[mt][nt][j] = 0.0f;

#pragma unroll
        for (int k0 = 0; k0 < 8; k0++) {
#pragma unroll
            for (int ks = 0; ks < 2; ks++) {
                uint32_t a[4][4], b[4][2];
                int kb = k0 * 64 + ks * 32;
#pragma unroll
                for (int mt = 0; mt < 4; mt++) {
                    int m = wm * 64 + mt * 16 + (sel & 1) * 8 + r8;
                    uint32_t ad = ayb + m * 528 + kb + ((sel >> 1) & 1) * 16;
                    asm volatile(
                        "ldmatrix.sync.aligned.m8n8.x4.shared.b16 {%0,%1,%2,%3}, [%4];"
                        : "=r"(a[mt][0]), "=r"(a[mt][1]), "=r"(a[mt][2]), "=r"(a[mt][3])
                        : "r"(ad));
                }
#pragma unroll
                for (int nt = 0; nt < 4; nt++) {
                    int n = wn * 32 + nt * 8 + br;
                    uint32_t ad = w2b + n * 528 + kb + bs * 16;
                    asm volatile(
                        "ldmatrix.sync.aligned.m8n8.x2.shared.b16 {%0,%1}, [%2];"
                        : "=r"(b[nt][0]), "=r"(b[nt][1]) : "r"(ad));
                }
#pragma unroll
                for (int mt = 0; mt < 4; mt++)
#pragma unroll
                    for (int nt = 0; nt < 4; nt++) {
                        asm volatile(
                            "mma.sync.aligned.m16n8k16.row.col.f32.f16.f16.f32 "
                            "{%0,%1,%2,%3}, {%4,%5,%6,%7}, {%8,%9}, {%0,%1,%2,%3};"
                            : "+f"(acc2[mt][nt][0]), "+f"(acc2[mt][nt][1]),
                              "+f"(acc2[mt][nt][2]), "+f"(acc2[mt][nt][3])
                            : "r"(a[mt][0]), "r"(a[mt][1]), "r"(a[mt][2]), "r"(a[mt][3]),
                              "r"(b[nt][0]), "r"(b[nt][1]));
                    }
            }
        }
        __syncthreads();   // y reads done; AY free

        // ---- write next A tile from registers ----
        if (hasNext) {
#pragma unroll
            for (int j = 0; j < 8; j++) {
                int i2 = tid + 256 * j;
                int r = i2 >> 4, c = i2 & 15;
                *(uint4*)(sm + AYO + r * 272 + c * 16) = pf[j];
            }
        }

        // ---- epilogue: global h16 or fused pool ----
        if (doPool) {
#pragma unroll
            for (int mt = 0; mt < 4; mt++) {
                int ra = row0 + wm * 64 + mt * 16 + g;
                int sgA = g_off[batch[ra]] + sgb[ra];
                int sgB = g_off[batch[ra + 8]] + sgb[ra + 8];
#pragma unroll
                for (int nt = 0; nt < 4; nt++) {
                    int col = wn * 32 + nt * 8 + tg * 2;
                    float2 bv = *(const float2*)(b2 + col);
                    float2 o0 = {acc2[mt][nt][0] + bv.x, acc2[mt][nt][1] + bv.y};
                    float2 o1 = {acc2[mt][nt][2] + bv.x, acc2[mt][nt][3] + bv.y};
                    red_add_v2(out + (size_t)sgA * DD + col, o0);
                    red_add_v2(out + (size_t)sgB * DD + col, o1);
                }
            }
        } else {
#pragma unroll
            for (int mt = 0; mt < 4; mt++) {
#pragma unroll
                for (int nt = 0; nt < 4; nt++) {
                    int col = wn * 32 + nt * 8 + tg * 2;
                    float2 bv = *(const float2*)(b2 + col);
                    int r0 = row0 + wm * 64 + mt * 16 + g;
                    float2 o0, o1;
                    o0.x = acc2[mt][nt][0] + bv.x;
                    o0.y = acc2[mt][nt][1] + bv.y;
                    o1.x = acc2[mt][nt][2] + bv.x;
                    o1.y = acc2[mt][nt][3] + bv.y;
                    if (doRelu2) {
                        o0.x = fmaxf(o0.x, 0.0f); o0.y = fmaxf(o0.y, 0.0f);
                        o1.x = fmaxf(o1.x, 0.0f); o1.y = fmaxf(o1.y, 0.0f);
                    }
                    __half2 p0 = __floats2half2_rn(o0.x, o0.y);
                    __half2 p1 = __floats2half2_rn(o1.x, o1.y);
                    *(__half2*)(H16 + (size_t)r0 * DD + col)       = p0;
                    *(__half2*)(H16 + (size_t)(r0 + 8) * DD + col) = p1;
                }
            }
        }
        __syncthreads();   // STS of next A visible before next GEMM1
    }
}

// ---------------- pooling helpers ---------------------------------------------
__global__ void prefix_kernel(const int* __restrict__ ns, int G) {
    if (blockIdx.x == 0 && threadIdx.x == 0) {
        int a = 0;
        for (int g = 0; g < G; ++g) { g_off[g] = a; a += ns[g]; }
    }
}

__global__ void zero_kernel(float* __restrict__ out, int n_out) {
    int i = blockIdx.x * blockDim.x + threadIdx.x;
    if (i < n_out) out[i] = 0.0f;
    if (i < TSG) g_cnt[i] = 0.0f;
}

__global__ void count_kernel(const int* __restrict__ batch,
                             const int* __restrict__ sgb, int Nn) {
    int i = blockIdx.x * blockDim.x + threadIdx.x;
    if (i < Nn) atomicAdd(&g_cnt[g_off[batch[i]] + sgb[i]], 1.0f);
}

__global__ void div_kernel(float* __restrict__ sums, int total) {
    int i = blockIdx.x * blockDim.x + threadIdx.x;
    if (i >= total) return;
    sums[i] /= fmaxf(g_cnt[i / DD], 1.0f);
}

// ---------------- launch ------------------------------------------------------
extern "C" void kernel_launch(void* const* d_in, const int* in_sizes, int n_in,
                              void* d_out, int out_size) {
    const float* x     = (const float*)d_in[0];
    const int*   edge  = (const int*)d_in[1];
    const int*   batch = (const int*)d_in[2];
    const int*   sgb   = (const int*)d_in[3];
    const int*   nsg   = (const int*)d_in[4];
    const float* W1  = (const float*)d_in[5];
    const float* b1  = (const float*)d_in[6];
    const float* W2  = (const float*)d_in[7];
    const float* b2  = (const float*)d_in[8];
    const float* eps = (const float*)d_in[9];
    float* out = (float*)d_out;

    int N = in_sizes[0] / DD;
    int E = in_sizes[1] / 2;
    int G = in_sizes[4];
    const int* src = edge;
    const int* dst = edge + E;

    void *ph16, *pa, *pw, *pc;
    cudaGetSymbolAddress(&ph16, g_hh16);
    cudaGetSymbolAddress(&pa, g_agg16);
    cudaGetSymbolAddress(&pw, g_w16t);
    cudaGetSymbolAddress(&pc, g_cur);
    __half* h16   = (__half*)ph16;
    __half* agg16 = (__half*)pa;
    __half* w16t  = (__half*)pw;

    static bool attrSet = false;
    if (!attrSet) {
        cudaFuncSetAttribute(mlp_fused,
                             cudaFuncAttributeMaxDynamicSharedMemorySize, SMEM_TOT);
        attrSet = true;
    }

    // one-time per launch: x->fp16, weights, CSR, pool metadata
    x2h_kernel<<<(N * DD / 4 + 255) / 256, 256>>>(x, N * DD / 4);
    convw_kernel<<<(LL * 65536 + 255) / 256, 256>>>(W1, W2);
    prefix_kernel<<<1, 32>>>(nsg, G);
    cudaMemsetAsync(pc, 0, (size_t)NN * 4, 0);
    hist_kernel<<<(E + 255) / 256, 256>>>(dst, E);
    scan1_kernel<<<NCHUNK, 256>>>();
    scan2_kernel<<<1, 512>>>();
    scan3_kernel<<<(NN + 255) / 256, 256>>>(E);
    cudaMemsetAsync(pc, 0, (size_t)NN * 4, 0);
    fill_kernel<<<(E + 255) / 256, 256>>>(src, dst, E);
    zero_kernel<<<(out_size + 255) / 256, 256>>>(out, out_size);
    count_kernel<<<(N + 255) / 256, 256>>>(batch, sgb, N);

    int ntiles = N / 128;
    int grid = 148 < ntiles ? 148 : ntiles;

    for (int l = 0; l < LL; l++) {
        gather_kernel<<<(int)(((long long)N * 32 + 255) / 256), 256>>>(eps, l, N);
        mlp_fused<<<grid, 256, SMEM_TOT>>>(
            agg16, w16t + (size_t)l * 65536, b1 + (size_t)l * 256,
            w16t + (size_t)l * 65536 + 32768, b2 + (size_t)l * 128,
            h16, batch, sgb, out, ntiles,
            (l < LL - 1) ? 1 : 0, (l == LL - 1) ? 1 : 0);
    }

    div_kernel<<<(out_size + 255) / 256, 256>>>(out, out_size);
}

// round 9
// speedup vs baseline: 1.0009x; 1.0009x over previous
#include <cuda_runtime.h>
#include <cuda_fp16.h>
#include <cstdint>
#include <cstddef>

#define NN  102400
#define EE  819200
#define DD  128
#define LL  5
#define TSG 1024
#define NCHUNK 400          // NN / 256

// ---------------- scratch (static device globals) ----------------------------
__device__ __half g_hh16[(size_t)NN * DD];       // fp16 activations (gather in)
__device__ __half g_agg16[(size_t)NN * DD];      // MLP input
__device__ __half g_w16t[(size_t)LL * 65536];    // transposed fp16 weights
__device__ int    g_rowptr[NN + 1];
__device__ int    g_cur[NN];                     // invariant: ==0 at call entry/exit
__device__ int    g_bsum[NCHUNK];
__device__ int    g_col[EE];
__device__ float  g_cnt[TSG];
__device__ int    g_off[64];

// ---------------- x -> fp16 (once) --------------------------------------------
__global__ void x2h_kernel(const float* __restrict__ x, int total4) {
    int i = blockIdx.x * blockDim.x + threadIdx.x;
    if (i >= total4) return;
    float4 v = ((const float4*)x)[i];
    __half2 h0 = __floats2half2_rn(v.x, v.y);
    __half2 h1 = __floats2half2_rn(v.z, v.w);
    uint2 o = {*(uint32_t*)&h0, *(uint32_t*)&h1};
    ((uint2*)g_hh16)[i] = o;
}

// ---------------- weight convert + transpose ---------------------------------
// per layer l: [0,32768): W1^T [n=256][k=128]; [32768,65536): W2^T [n=128][k=256]
__global__ void convw_kernel(const float* __restrict__ W1,
                             const float* __restrict__ W2) {
    int i = blockIdx.x * blockDim.x + threadIdx.x;
    if (i >= LL * 65536) return;
    int l = i >> 16, r = i & 65535;
    float v;
    if (r < 32768) {
        int n = r >> 7, k = r & 127;
        v = W1[(size_t)l * 32768 + k * 256 + n];
    } else {
        int r2 = r - 32768;
        int n = r2 >> 8, k = r2 & 255;
        v = W2[(size_t)l * 32768 + k * 128 + n];
    }
    g_w16t[i] = __float2half_rn(v);
}

// ---------------- CSR build (4 launches, no memsets) --------------------------
__global__ void hist_kernel(const int* __restrict__ dst, int E) {
    int e = blockIdx.x * blockDim.x + threadIdx.x;
    if (e < E) atomicAdd(&g_cur[dst[e]], 1);
}

__global__ void scan1_kernel() {
    __shared__ int s[256];
    int t = threadIdx.x, i = blockIdx.x * 256 + t;
    int v = g_cur[i];
    s[t] = v;
    __syncthreads();
#pragma unroll
    for (int o = 1; o < 256; o <<= 1) {
        int u = (t >= o) ? s[t - o] : 0;
        __syncthreads();
        s[t] += u;
        __syncthreads();
    }
    g_rowptr[i] = s[t] - v;                 // exclusive within block
    if (t == 255) g_bsum[blockIdx.x] = s[255];
}

// fused scan2+scan3: each block computes its own prefix of g_bsum, applies it.
__global__ void scan23_kernel(int E) {
    __shared__ int s[256];
    int b = blockIdx.x, t = threadIdx.x;
    int partial = 0;
    for (int j = t; j < b; j += 256) partial += g_bsum[j];
    s[t] = partial;
    __syncthreads();
#pragma unroll
    for (int o = 128; o > 0; o >>= 1) {
        if (t < o) s[t] += s[t + o];
        __syncthreads();
    }
    int off = s[0];
    g_rowptr[b * 256 + t] += off;
    if (b == 0 && t == 0) g_rowptr[NN] = E;
}

// self-restoring fill: drains g_cur back to 0 (row-internal order arbitrary).
__global__ void fill_kernel(const int* __restrict__ src,
                            const int* __restrict__ dst, int E) {
    int e = blockIdx.x * blockDim.x + threadIdx.x;
    if (e >= E) return;
    int d = dst[e];
    int p = g_rowptr[d] + atomicSub(&g_cur[d], 1) - 1;
    g_col[p] = src[e];
}

// ---------------- gather: agg16[d] = fp16((1+eps)h[d] + sum h[nb]) ------------
__device__ __forceinline__ void acc4(float* acc, uint2 v) {
    float2 f0 = __half22float2(*(const __half2*)&v.x);
    float2 f1 = __half22float2(*(const __half2*)&v.y);
    acc[0] += f0.x; acc[1] += f0.y; acc[2] += f1.x; acc[3] += f1.y;
}

__global__ void gather_kernel(const float* __restrict__ eps, int l, int Nn) {
    long long tid = (long long)blockIdx.x * blockDim.x + threadIdx.x;
    int node = (int)(tid >> 5);
    if (node >= Nn) return;
    int lane = (int)(tid & 31);
    float e1 = 1.0f + eps[l];
    const uint2* hv = (const uint2*)g_hh16;

    float acc[4];
    {
        uint2 v = hv[(size_t)node * 32 + lane];
        float2 f0 = __half22float2(*(const __half2*)&v.x);
        float2 f1 = __half22float2(*(const __half2*)&v.y);
        acc[0] = e1 * f0.x; acc[1] = e1 * f0.y;
        acc[2] = e1 * f1.x; acc[3] = e1 * f1.y;
    }

    int i = g_rowptr[node], t = g_rowptr[node + 1];
    for (; i + 4 <= t; i += 4) {
        int n0 = g_col[i], n1 = g_col[i + 1];
        int n2 = g_col[i + 2], n3 = g_col[i + 3];
        uint2 v0 = hv[(size_t)n0 * 32 + lane];
        uint2 v1 = hv[(size_t)n1 * 32 + lane];
        uint2 v2 = hv[(size_t)n2 * 32 + lane];
        uint2 v3 = hv[(size_t)n3 * 32 + lane];
        acc4(acc, v0); acc4(acc, v1); acc4(acc, v2); acc4(acc, v3);
    }
    for (; i < t; i++) acc4(acc, hv[(size_t)g_col[i] * 32 + lane]);

    __half2 h0 = __floats2half2_rn(acc[0], acc[1]);
    __half2 h1 = __floats2half2_rn(acc[2], acc[3]);
    uint2 o = {*(uint32_t*)&h0, *(uint32_t*)&h1};
    ((uint2*)(g_agg16 + (size_t)node * DD))[lane] = o;
}

// ---------------- persistent fused MLP ----------------------------------------
// grid = 148 persistent CTAs; each strides tiles of 128 rows.
// SMEM: W1 (stride 272, 69632B) | W2 (stride 528, 67584B) | AY (67584B)
#define CP16(smb, g) \
    asm volatile("cp.async.cg.shared.global [%0], [%1], 16;" :: "r"(smb), "l"(g))
#define W1O 0
#define W2O 69632
#define AYO 137216
#define SMEM_TOT 204800

__device__ __forceinline__ void red_add_v2(float* p, float2 v) {
    asm volatile("red.global.add.v2.f32 [%0], {%1,%2};"
                 :: "l"(p), "f"(v.x), "f"(v.y) : "memory");
}

__global__ __launch_bounds__(256) void mlp_fused(
    const __half* __restrict__ A, const __half* __restrict__ W1t,
    const float* __restrict__ b1, const __half* __restrict__ W2t,
    const float* __restrict__ b2, __half* __restrict__ H16,
    const int* __restrict__ batch, const int* __restrict__ sgb,
    float* __restrict__ out, int ntiles, int doRelu2, int doPool) {
    extern __shared__ char sm[];
    uint32_t sb  = (uint32_t)__cvta_generic_to_shared(sm);
    uint32_t w1b = sb + W1O, w2b = sb + W2O, ayb = sb + AYO;

    int tid  = threadIdx.x;
    int lane = tid & 31;
    int wid  = tid >> 5;
    int wm   = wid & 1;                      // 2 warp rows of 64
    int wn   = wid >> 1;                     // 4 warp cols
    int stride = gridDim.x;

    // ---- group 0: W1 + A(tile0); group 1: W2 ----
    for (int i = tid; i < 4096; i += 256) {  // W1: 256 rows x 16 chunks
        int r = i >> 4, c = i & 15;
        CP16(w1b + r * 272 + c * 16, W1t + (size_t)r * 128 + c * 8);
    }
    {
        int row0 = blockIdx.x * 128;
        for (int i = tid; i < 2048; i += 256) {  // A: 128 rows x 16 chunks
            int r = i >> 4, c = i & 15;
            CP16(ayb + r * 272 + c * 16, A + (size_t)(row0 + r) * 128 + c * 8);
        }
    }
    asm volatile("cp.async.commit_group;");
    for (int i = tid; i < 4096; i += 256) {  // W2: 128 rows x 32 chunks
        int r = i >> 5, c = i & 31;
        CP16(w2b + r * 528 + c * 16, W2t + (size_t)r * 256 + c * 8);
    }
    asm volatile("cp.async.commit_group;");
    asm volatile("cp.async.wait_group 1;");
    __syncthreads();

    int r8  = lane & 7;
    int sel = lane >> 3;
    int ll  = lane & 15;
    int bs  = ll >> 3;
    int br  = ll & 7;
    int g   = lane >> 2;
    int tg  = lane & 3;

    bool firstIter = true;
    for (int tile = blockIdx.x; tile < ntiles; tile += stride) {
        int row0 = tile * 128;
        int nextTile = tile + stride;
        bool hasNext = nextTile < ntiles;

        // ---- prefetch next A tile into registers (consumed post-GEMM2) ----
        uint4 pf[8];
        if (hasNext) {
            const uint4* Ag = (const uint4*)(A + (size_t)nextTile * 128 * 128);
#pragma unroll
            for (int j = 0; j < 8; j++) pf[j] = Ag[tid + 256 * j];
        }

        // ============ GEMM1: y[128,256] = A[128,128] @ W1 ============
        float acc[4][8][4];
#pragma unroll
        for (int mt = 0; mt < 4; mt++)
#pragma unroll
            for (int nt = 0; nt < 8; nt++)
#pragma unroll
                for (int j = 0; j < 4; j++) acc[mt][nt][j] = 0.0f;

#pragma unroll
        for (int k0 = 0; k0 < 4; k0++) {
#pragma unroll
            for (int ks = 0; ks < 2; ks++) {
                uint32_t a[4][4], b[8][2];
                int kb = k0 * 64 + ks * 32;
#pragma unroll
                for (int mt = 0; mt < 4; mt++) {
                    int m = wm * 64 + mt * 16 + (sel & 1) * 8 + r8;
                    uint32_t ad = ayb + m * 272 + kb + ((sel >> 1) & 1) * 16;
                    asm volatile(
                        "ldmatrix.sync.aligned.m8n8.x4.shared.b16 {%0,%1,%2,%3}, [%4];"
                        : "=r"(a[mt][0]), "=r"(a[mt][1]), "=r"(a[mt][2]), "=r"(a[mt][3])
                        : "r"(ad));
                }
#pragma unroll
                for (int nt = 0; nt < 8; nt++) {
                    int n = wn * 64 + nt * 8 + br;
                    uint32_t ad = w1b + n * 272 + kb + bs * 16;
                    asm volatile(
                        "ldmatrix.sync.aligned.m8n8.x2.shared.b16 {%0,%1}, [%2];"
                        : "=r"(b[nt][0]), "=r"(b[nt][1]) : "r"(ad));
                }
#pragma unroll
                for (int mt = 0; mt < 4; mt++)
#pragma unroll
                    for (int nt = 0; nt < 8; nt++) {
                        asm volatile(
                            "mma.sync.aligned.m16n8k16.row.col.f32.f16.f16.f32 "
                            "{%0,%1,%2,%3}, {%4,%5,%6,%7}, {%8,%9}, {%0,%1,%2,%3};"
                            : "+f"(acc[mt][nt][0]), "+f"(acc[mt][nt][1]),
                              "+f"(acc[mt][nt][2]), "+f"(acc[mt][nt][3])
                            : "r"(a[mt][0]), "r"(a[mt][1]), "r"(a[mt][2]), "r"(a[mt][3]),
                              "r"(b[nt][0]), "r"(b[nt][1]));
                    }
            }
        }
        __syncthreads();   // A reads done; AY becomes y

        // ---- bias + relu + fp16, store y to SMEM (stride 528) ----
#pragma unroll
        for (int mt = 0; mt < 4; mt++) {
#pragma unroll
            for (int nt = 0; nt < 8; nt++) {
                int col = wn * 64 + nt * 8 + tg * 2;
                float2 bv = *(const float2*)(b1 + col);
                int r0 = wm * 64 + mt * 16 + g;
                float f0 = fmaxf(acc[mt][nt][0] + bv.x, 0.0f);
                float f1 = fmaxf(acc[mt][nt][1] + bv.y, 0.0f);
                float f2 = fmaxf(acc[mt][nt][2] + bv.x, 0.0f);
                float f3 = fmaxf(acc[mt][nt][3] + bv.y, 0.0f);
                __half2 p0 = __floats2half2_rn(f0, f1);
                __half2 p1 = __floats2half2_rn(f2, f3);
                *(__half2*)(sm + AYO + r0 * 528 + col * 2)       = p0;
                *(__half2*)(sm + AYO + (r0 + 8) * 528 + col * 2) = p1;
            }
        }
        if (firstIter) {
            asm volatile("cp.async.wait_group 0;");   // W2 resident
            firstIter = false;
        }
        __syncthreads();

        // ============ GEMM2: h[128,128] = y[128,256] @ W2 ============
        float acc2[4][4][4];
#pragma unroll
        for (int mt = 0; mt < 4; mt++)
#pragma unroll
            for (int nt = 0; nt < 4; nt++)
#pragma unroll
                for (int j = 0; j < 4; j++) acc2[mt][nt][j] = 0.0f;

#pragma unroll
        for (int k0 = 0; k0 < 8; k0++) {
#pragma unroll
            for (int ks = 0; ks < 2; ks++) {
                uint32_t a[4][4], b[4][2];
                int kb = k0 * 64 + ks * 32;
#pragma unroll
                for (int mt = 0; mt < 4; mt++) {
                    int m = wm * 64 + mt * 16 + (sel & 1) * 8 + r8;
                    uint32_t ad = ayb + m * 528 + kb + ((sel >> 1) & 1) * 16;
                    asm volatile(
                        "ldmatrix.sync.aligned.m8n8.x4.shared.b16 {%0,%1,%2,%3}, [%4];"
                        : "=r"(a[mt][0]), "=r"(a[mt][1]), "=r"(a[mt][2]), "=r"(a[mt][3])
                        : "r"(ad));
                }
#pragma unroll
                for (int nt = 0; nt < 4; nt++) {
                    int n = wn * 32 + nt * 8 + br;
                    uint32_t ad = w2b + n * 528 + kb + bs * 16;
                    asm volatile(
                        "ldmatrix.sync.aligned.m8n8.x2.shared.b16 {%0,%1}, [%2];"
                        : "=r"(b[nt][0]), "=r"(b[nt][1]) : "r"(ad));
                }
#pragma unroll
                for (int mt = 0; mt < 4; mt++)
#pragma unroll
                    for (int nt = 0; nt < 4; nt++) {
                        asm volatile(
                            "mma.sync.aligned.m16n8k16.row.col.f32.f16.f16.f32 "
                            "{%0,%1,%2,%3}, {%4,%5,%6,%7}, {%8,%9}, {%0,%1,%2,%3};"
                            : "+f"(acc2[mt][nt][0]), "+f"(acc2[mt][nt][1]),
                              "+f"(acc2[mt][nt][2]), "+f"(acc2[mt][nt][3])
                            : "r"(a[mt][0]), "r"(a[mt][1]), "r"(a[mt][2]), "r"(a[mt][3]),
                              "r"(b[nt][0]), "r"(b[nt][1]));
                    }
            }
        }
        __syncthreads();   // y reads done; AY free

        // ---- write next A tile from registers ----
        if (hasNext) {
#pragma unroll
            for (int j = 0; j < 8; j++) {
                int i2 = tid + 256 * j;
                int r = i2 >> 4, c = i2 & 15;
                *(uint4*)(sm + AYO + r * 272 + c * 16) = pf[j];
            }
        }

        // ---- epilogue: global h16 or fused pool ----
        if (doPool) {
#pragma unroll
            for (int mt = 0; mt < 4; mt++) {
                int ra = row0 + wm * 64 + mt * 16 + g;
                int sgA = g_off[batch[ra]] + sgb[ra];
                int sgB = g_off[batch[ra + 8]] + sgb[ra + 8];
#pragma unroll
                for (int nt = 0; nt < 4; nt++) {
                    int col = wn * 32 + nt * 8 + tg * 2;
                    float2 bv = *(const float2*)(b2 + col);
                    float2 o0 = {acc2[mt][nt][0] + bv.x, acc2[mt][nt][1] + bv.y};
                    float2 o1 = {acc2[mt][nt][2] + bv.x, acc2[mt][nt][3] + bv.y};
                    red_add_v2(out + (size_t)sgA * DD + col, o0);
                    red_add_v2(out + (size_t)sgB * DD + col, o1);
                }
            }
        } else {
#pragma unroll
            for (int mt = 0; mt < 4; mt++) {
#pragma unroll
                for (int nt = 0; nt < 4; nt++) {
                    int col = wn * 32 + nt * 8 + tg * 2;
                    float2 bv = *(const float2*)(b2 + col);
                    int r0 = row0 + wm * 64 + mt * 16 + g;
                    float2 o0, o1;
                    o0.x = acc2[mt][nt][0] + bv.x;
                    o0.y = acc2[mt][nt][1] + bv.y;
                    o1.x = acc2[mt][nt][2] + bv.x;
                    o1.y = acc2[mt][nt][3] + bv.y;
                    if (doRelu2) {
                        o0.x = fmaxf(o0.x, 0.0f); o0.y = fmaxf(o0.y, 0.0f);
                        o1.x = fmaxf(o1.x, 0.0f); o1.y = fmaxf(o1.y, 0.0f);
                    }
                    __half2 p0 = __floats2half2_rn(o0.x, o0.y);
                    __half2 p1 = __floats2half2_rn(o1.x, o1.y);
                    *(__half2*)(H16 + (size_t)r0 * DD + col)       = p0;
                    *(__half2*)(H16 + (size_t)(r0 + 8) * DD + col) = p1;
                }
            }
        }
        __syncthreads();   // STS of next A visible before next GEMM1
    }
}

// ---------------- pooling helpers ---------------------------------------------
__global__ void prefix_kernel(const int* __restrict__ ns, int G) {
    if (blockIdx.x == 0 && threadIdx.x == 0) {
        int a = 0;
        for (int g = 0; g < G; ++g) { g_off[g] = a; a += ns[g]; }
    }
}

__global__ void zero_kernel(float* __restrict__ out, int n_out) {
    int i = blockIdx.x * blockDim.x + threadIdx.x;
    if (i < n_out) out[i] = 0.0f;
    if (i < TSG) g_cnt[i] = 0.0f;
}

__global__ void count_kernel(const int* __restrict__ batch,
                             const int* __restrict__ sgb, int Nn) {
    int i = blockIdx.x * blockDim.x + threadIdx.x;
    if (i < Nn) atomicAdd(&g_cnt[g_off[batch[i]] + sgb[i]], 1.0f);
}

__global__ void div_kernel(float* __restrict__ sums, int total) {
    int i = blockIdx.x * blockDim.x + threadIdx.x;
    if (i >= total) return;
    sums[i] /= fmaxf(g_cnt[i / DD], 1.0f);
}

// ---------------- launch ------------------------------------------------------
extern "C" void kernel_launch(void* const* d_in, const int* in_sizes, int n_in,
                              void* d_out, int out_size) {
    const float* x     = (const float*)d_in[0];
    const int*   edge  = (const int*)d_in[1];
    const int*   batch = (const int*)d_in[2];
    const int*   sgb   = (const int*)d_in[3];
    const int*   nsg   = (const int*)d_in[4];
    const float* W1  = (const float*)d_in[5];
    const float* b1  = (const float*)d_in[6];
    const float* W2  = (const float*)d_in[7];
    const float* b2  = (const float*)d_in[8];
    const float* eps = (const float*)d_in[9];
    float* out = (float*)d_out;

    int N = in_sizes[0] / DD;
    int E = in_sizes[1] / 2;
    int G = in_sizes[4];
    const int* src = edge;
    const int* dst = edge + E;

    void *ph16, *pa, *pw;
    cudaGetSymbolAddress(&ph16, g_hh16);
    cudaGetSymbolAddress(&pa, g_agg16);
    cudaGetSymbolAddress(&pw, g_w16t);
    __half* h16   = (__half*)ph16;
    __half* agg16 = (__half*)pa;
    __half* w16t  = (__half*)pw;

    static bool attrSet = false;
    if (!attrSet) {
        cudaFuncSetAttribute(mlp_fused,
                             cudaFuncAttributeMaxDynamicSharedMemorySize, SMEM_TOT);
        attrSet = true;
    }

    // CSR build (g_cur==0 invariant; fill drains it back to 0)
    hist_kernel<<<(E + 255) / 256, 256>>>(dst, E);                 // launch 0
    scan1_kernel<<<NCHUNK, 256>>>();                               // launch 1
    scan23_kernel<<<NCHUNK, 256>>>(E);                             // launch 2
    fill_kernel<<<(E + 255) / 256, 256>>>(src, dst, E);            // launch 3
    x2h_kernel<<<(N * DD / 4 + 255) / 256, 256>>>(x, N * DD / 4);  // launch 4

    int ntiles = N / 128;
    int grid = 148 < ntiles ? 148 : ntiles;

    // launch 5 == gather(l=0)  -> profiled by ncu (-s 5 -c 1)
    gather_kernel<<<(int)(((long long)N * 32 + 255) / 256), 256>>>(eps, 0, N);

    convw_kernel<<<(LL * 65536 + 255) / 256, 256>>>(W1, W2);
    prefix_kernel<<<1, 32>>>(nsg, G);
    zero_kernel<<<(out_size + 255) / 256, 256>>>(out, out_size);

    for (int l = 0; l < LL; l++) {
        if (l > 0)
            gather_kernel<<<(int)(((long long)N * 32 + 255) / 256), 256>>>(eps, l, N);
        mlp_fused<<<grid, 256, SMEM_TOT>>>(
            agg16, w16t + (size_t)l * 65536, b1 + (size_t)l * 256,
            w16t + (size_t)l * 65536 + 32768, b2 + (size_t)l * 128,
            h16, batch, sgb, out, ntiles,
            (l < LL - 1) ? 1 : 0, (l == LL - 1) ? 1 : 0);
    }

    count_kernel<<<(N + 255) / 256, 256>>>(batch, sgb, N);
    div_kernel<<<(out_size + 255) / 256, 256>>>(out, out_size);
}

// round 10
// speedup vs baseline: 1.0191x; 1.0182x over previous
#include <cuda_runtime.h>
#include <cuda_fp16.h>
#include <cstdint>
#include <cstddef>

#define NN  102400
#define EE  819200
#define DD  128
#define LL  5
#define TSG 1024
#define NCHUNK 400          // NN / 256

// ---------------- scratch (static device globals) ----------------------------
__device__ __half g_hh16[(size_t)NN * DD];       // fp16 activations (gather in)
__device__ __half g_agg16[(size_t)NN * DD];      // MLP input
__device__ __half g_w16t[(size_t)LL * 65536];    // transposed fp16 weights
__device__ int    g_rowptr[NN + 1];
__device__ int    g_cur[NN];                     // invariant: ==0 at call entry/exit
__device__ int    g_bsum[NCHUNK];
__device__ int    g_col[EE];
__device__ float  g_cnt[TSG];
__device__ int    g_off[64];

// ---------------- mega setup: hist | x2h | convw | prefix | zero --------------
// block ranges:
//   [0, 3200)        hist: atomicAdd degree counters
//   [3200, 16000)    x2h : x fp32 -> fp16
//   [16000, 17280)   convw: weight convert+transpose
//   [17280]          prefix over num_subgraphs
//   (17280, 17280+ZB] zero out + g_cnt
__global__ void setup_kernel(const int* __restrict__ dst, int E,
                             const float* __restrict__ x, int total4,
                             const float* __restrict__ W1,
                             const float* __restrict__ W2,
                             const int* __restrict__ nsg, int G,
                             float* __restrict__ out, int n_out) {
    int b = blockIdx.x, t = threadIdx.x;
    if (b < 3200) {
        int e = b * 256 + t;
        if (e < E) atomicAdd(&g_cur[dst[e]], 1);
    } else if (b < 16000) {
        int i = (b - 3200) * 256 + t;
        if (i < total4) {
            float4 v = ((const float4*)x)[i];
            __half2 h0 = __floats2half2_rn(v.x, v.y);
            __half2 h1 = __floats2half2_rn(v.z, v.w);
            uint2 o = {*(uint32_t*)&h0, *(uint32_t*)&h1};
            ((uint2*)g_hh16)[i] = o;
        }
    } else if (b < 17280) {
        int i = (b - 16000) * 256 + t;
        int l = i >> 16, r = i & 65535;
        float v;
        if (r < 32768) {
            int n = r >> 7, k = r & 127;
            v = W1[(size_t)l * 32768 + k * 256 + n];
        } else {
            int r2 = r - 32768;
            int n = r2 >> 8, k = r2 & 255;
            v = W2[(size_t)l * 32768 + k * 128 + n];
        }
        g_w16t[i] = __float2half_rn(v);
    } else if (b == 17280) {
        if (t == 0) {
            int a = 0;
            for (int g = 0; g < G; ++g) { g_off[g] = a; a += nsg[g]; }
        }
    } else {
        int i = (b - 17281) * 256 + t;
        if (i < n_out) out[i] = 0.0f;
        if (i < TSG) g_cnt[i] = 0.0f;
    }
}

// ---------------- CSR build ----------------------------------------------------
__global__ void scan1_kernel() {
    __shared__ int s[256];
    int t = threadIdx.x, i = blockIdx.x * 256 + t;
    int v = g_cur[i];
    s[t] = v;
    __syncthreads();
#pragma unroll
    for (int o = 1; o < 256; o <<= 1) {
        int u = (t >= o) ? s[t - o] : 0;
        __syncthreads();
        s[t] += u;
        __syncthreads();
    }
    g_rowptr[i] = s[t] - v;                 // exclusive within block
    if (t == 255) g_bsum[blockIdx.x] = s[255];
}

// fused scan2+scan3: each block computes its own prefix of g_bsum, applies it.
__global__ void scan23_kernel(int E) {
    __shared__ int s[256];
    int b = blockIdx.x, t = threadIdx.x;
    int partial = 0;
    for (int j = t; j < b; j += 256) partial += g_bsum[j];
    s[t] = partial;
    __syncthreads();
#pragma unroll
    for (int o = 128; o > 0; o >>= 1) {
        if (t < o) s[t] += s[t + o];
        __syncthreads();
    }
    int off = s[0];
    g_rowptr[b * 256 + t] += off;
    if (b == 0 && t == 0) g_rowptr[NN] = E;
}

// self-restoring fill: drains g_cur back to 0 (row-internal order arbitrary).
__global__ void fill_kernel(const int* __restrict__ src,
                            const int* __restrict__ dst, int E) {
    int e = blockIdx.x * blockDim.x + threadIdx.x;
    if (e >= E) return;
    int d = dst[e];
    int p = g_rowptr[d] + atomicSub(&g_cur[d], 1) - 1;
    g_col[p] = src[e];
}

// ---------------- gather: agg16[d] = fp16((1+eps)h[d] + sum h[nb]) ------------
__device__ __forceinline__ void acc4(float* acc, uint2 v) {
    float2 f0 = __half22float2(*(const __half2*)&v.x);
    float2 f1 = __half22float2(*(const __half2*)&v.y);
    acc[0] += f0.x; acc[1] += f0.y; acc[2] += f1.x; acc[3] += f1.y;
}

__global__ void gather_kernel(const float* __restrict__ eps, int l, int Nn) {
    long long tid = (long long)blockIdx.x * blockDim.x + threadIdx.x;
    int node = (int)(tid >> 5);
    if (node >= Nn) return;
    int lane = (int)(tid & 31);
    float e1 = 1.0f + eps[l];
    const uint2* hv = (const uint2*)g_hh16;

    float acc[4];
    {
        uint2 v = hv[(size_t)node * 32 + lane];
        float2 f0 = __half22float2(*(const __half2*)&v.x);
        float2 f1 = __half22float2(*(const __half2*)&v.y);
        acc[0] = e1 * f0.x; acc[1] = e1 * f0.y;
        acc[2] = e1 * f1.x; acc[3] = e1 * f1.y;
    }

    int i = g_rowptr[node], t = g_rowptr[node + 1];
    for (; i + 4 <= t; i += 4) {
        int n0 = g_col[i], n1 = g_col[i + 1];
        int n2 = g_col[i + 2], n3 = g_col[i + 3];
        uint2 v0 = hv[(size_t)n0 * 32 + lane];
        uint2 v1 = hv[(size_t)n1 * 32 + lane];
        uint2 v2 = hv[(size_t)n2 * 32 + lane];
        uint2 v3 = hv[(size_t)n3 * 32 + lane];
        acc4(acc, v0); acc4(acc, v1); acc4(acc, v2); acc4(acc, v3);
    }
    for (; i < t; i++) acc4(acc, hv[(size_t)g_col[i] * 32 + lane]);

    __half2 h0 = __floats2half2_rn(acc[0], acc[1]);
    __half2 h1 = __floats2half2_rn(acc[2], acc[3]);
    uint2 o = {*(uint32_t*)&h0, *(uint32_t*)&h1};
    ((uint2*)(g_agg16 + (size_t)node * DD))[lane] = o;
}

// ---------------- persistent fused MLP ----------------------------------------
// grid = 148 persistent CTAs; each strides tiles of 128 rows.
// SMEM: W1 (stride 272, 69632B) | W2 (stride 528, 67584B) | AY (67584B)
#define CP16(smb, g) \
    asm volatile("cp.async.cg.shared.global [%0], [%1], 16;" :: "r"(smb), "l"(g))
#define W1O 0
#define W2O 69632
#define AYO 137216
#define SMEM_TOT 204800

__device__ __forceinline__ void red_add_v2(float* p, float2 v) {
    asm volatile("red.global.add.v2.f32 [%0], {%1,%2};"
                 :: "l"(p), "f"(v.x), "f"(v.y) : "memory");
}

__global__ __launch_bounds__(256) void mlp_fused(
    const __half* __restrict__ A, const __half* __restrict__ W1t,
    const float* __restrict__ b1, const __half* __restrict__ W2t,
    const float* __restrict__ b2, __half* __restrict__ H16,
    const int* __restrict__ batch, const int* __restrict__ sgb,
    float* __restrict__ out, int ntiles, int doRelu2, int doPool) {
    extern __shared__ char sm[];
    uint32_t sb  = (uint32_t)__cvta_generic_to_shared(sm);
    uint32_t w1b = sb + W1O, w2b = sb + W2O, ayb = sb + AYO;

    int tid  = threadIdx.x;
    int lane = tid & 31;
    int wid  = tid >> 5;
    int wm   = wid & 1;                      // 2 warp rows of 64
    int wn   = wid >> 1;                     // 4 warp cols
    int stride = gridDim.x;

    // ---- group 0: W1 + A(tile0); group 1: W2 ----
    for (int i = tid; i < 4096; i += 256) {  // W1: 256 rows x 16 chunks
        int r = i >> 4, c = i & 15;
        CP16(w1b + r * 272 + c * 16, W1t + (size_t)r * 128 + c * 8);
    }
    {
        int row0 = blockIdx.x * 128;
        for (int i = tid; i < 2048; i += 256) {  // A: 128 rows x 16 chunks
            int r = i >> 4, c = i & 15;
            CP16(ayb + r * 272 + c * 16, A + (size_t)(row0 + r) * 128 + c * 8);
        }
    }
    asm volatile("cp.async.commit_group;");
    for (int i = tid; i < 4096; i += 256) {  // W2: 128 rows x 32 chunks
        int r = i >> 5, c = i & 31;
        CP16(w2b + r * 528 + c * 16, W2t + (size_t)r * 256 + c * 8);
    }
    asm volatile("cp.async.commit_group;");
    asm volatile("cp.async.wait_group 1;");
    __syncthreads();

    int r8  = lane & 7;
    int sel = lane >> 3;
    int ll  = lane & 15;
    int bs  = ll >> 3;
    int br  = ll & 7;
    int g   = lane >> 2;
    int tg  = lane & 3;

    bool firstIter = true;
    for (int tile = blockIdx.x; tile < ntiles; tile += stride) {
        int row0 = tile * 128;
        int nextTile = tile + stride;
        bool hasNext = nextTile < ntiles;

        // ---- prefetch next A tile into registers (consumed post-GEMM2) ----
        uint4 pf[8];
        if (hasNext) {
            const uint4* Ag = (const uint4*)(A + (size_t)nextTile * 128 * 128);
#pragma unroll
            for (int j = 0; j < 8; j++) pf[j] = Ag[tid + 256 * j];
        }

        // ============ GEMM1: y[128,256] = A[128,128] @ W1 ============
        float acc[4][8][4];
#pragma unroll
        for (int mt = 0; mt < 4; mt++)
#pragma unroll
            for (int nt = 0; nt < 8; nt++)
#pragma unroll
                for (int j = 0; j < 4; j++) acc[mt][nt][j] = 0.0f;

#pragma unroll
        for (int k0 = 0; k0 < 4; k0++) {
#pragma unroll
            for (int ks = 0; ks < 2; ks++) {
                uint32_t a[4][4], b[8][2];
                int kb = k0 * 64 + ks * 32;
#pragma unroll
                for (int mt = 0; mt < 4; mt++) {
                    int m = wm * 64 + mt * 16 + (sel & 1) * 8 + r8;
                    uint32_t ad = ayb + m * 272 + kb + ((sel >> 1) & 1) * 16;
                    asm volatile(
                        "ldmatrix.sync.aligned.m8n8.x4.shared.b16 {%0,%1,%2,%3}, [%4];"
                        : "=r"(a[mt][0]), "=r"(a[mt][1]), "=r"(a[mt][2]), "=r"(a[mt][3])
                        : "r"(ad));
                }
#pragma unroll
                for (int nt = 0; nt < 8; nt++) {
                    int n = wn * 64 + nt * 8 + br;
                    uint32_t ad = w1b + n * 272 + kb + bs * 16;
                    asm volatile(
                        "ldmatrix.sync.aligned.m8n8.x2.shared.b16 {%0,%1}, [%2];"
                        : "=r"(b[nt][0]), "=r"(b[nt][1]) : "r"(ad));
                }
#pragma unroll
                for (int mt = 0; mt < 4; mt++)
#pragma unroll
                    for (int nt = 0; nt < 8; nt++) {
                        asm volatile(
                            "mma.sync.aligned.m16n8k16.row.col.f32.f16.f16.f32 "
                            "{%0,%1,%2,%3}, {%4,%5,%6,%7}, {%8,%9}, {%0,%1,%2,%3};"
                            : "+f"(acc[mt][nt][0]), "+f"(acc[mt][nt][1]),
                              "+f"(acc[mt][nt][2]), "+f"(acc[mt][nt][3])
                            : "r"(a[mt][0]), "r"(a[mt][1]), "r"(a[mt][2]), "r"(a[mt][3]),
                              "r"(b[nt][0]), "r"(b[nt][1]));
                    }
            }
        }
        __syncthreads();   // A reads done; AY becomes y

        // ---- bias + relu + fp16, store y to SMEM (stride 528) ----
#pragma unroll
        for (int mt = 0; mt < 4; mt++) {
#pragma unroll
            for (int nt = 0; nt < 8; nt++) {
                int col = wn * 64 + nt * 8 + tg * 2;
                float2 bv = *(const float2*)(b1 + col);
                int r0 = wm * 64 + mt * 16 + g;
                float f0 = fmaxf(acc[mt][nt][0] + bv.x, 0.0f);
                float f1 = fmaxf(acc[mt][nt][1] + bv.y, 0.0f);
                float f2 = fmaxf(acc[mt][nt][2] + bv.x, 0.0f);
                float f3 = fmaxf(acc[mt][nt][3] + bv.y, 0.0f);
                __half2 p0 = __floats2half2_rn(f0, f1);
                __half2 p1 = __floats2half2_rn(f2, f3);
                *(__half2*)(sm + AYO + r0 * 528 + col * 2)       = p0;
                *(__half2*)(sm + AYO + (r0 + 8) * 528 + col * 2) = p1;
            }
        }
        if (firstIter) {
            asm volatile("cp.async.wait_group 0;");   // W2 resident
            firstIter = false;
        }
        __syncthreads();

        // ============ GEMM2: h[128,128] = y[128,256] @ W2 ============
        float acc2[4][4][4];
#pragma unroll
        for (int mt = 0; mt < 4; mt++)
#pragma unroll
            for (int nt = 0; nt < 4; nt++)
#pragma unroll
                for (int j = 0; j < 4; j++) acc2[mt][nt][j] = 0.0f;

#pragma unroll
        for (int k0 = 0; k0 < 8; k0++) {
#pragma unroll
            for (int ks = 0; ks < 2; ks++) {
                uint32_t a[4][4], b[4][2];
                int kb = k0 * 64 + ks * 32;
#pragma unroll
                for (int mt = 0; mt < 4; mt++) {
                    int m = wm * 64 + mt * 16 + (sel & 1) * 8 + r8;
                    uint32_t ad = ayb + m * 528 + kb + ((sel >> 1) & 1) * 16;
                    asm volatile(
                        "ldmatrix.sync.aligned.m8n8.x4.shared.b16 {%0,%1,%2,%3}, [%4];"
                        : "=r"(a[mt][0]), "=r"(a[mt][1]), "=r"(a[mt][2]), "=r"(a[mt][3])
                        : "r"(ad));
                }
#pragma unroll
                for (int nt = 0; nt < 4; nt++) {
                    int n = wn * 32 + nt * 8 + br;
                    uint32_t ad = w2b + n * 528 + kb + bs * 16;
                    asm volatile(
                        "ldmatrix.sync.aligned.m8n8.x2.shared.b16 {%0,%1}, [%2];"
                        : "=r"(b[nt][0]), "=r"(b[nt][1]) : "r"(ad));
                }
#pragma unroll
                for (int mt = 0; mt < 4; mt++)
#pragma unroll
                    for (int nt = 0; nt < 4; nt++) {
                        asm volatile(
                            "mma.sync.aligned.m16n8k16.row.col.f32.f16.f16.f32 "
                            "{%0,%1,%2,%3}, {%4,%5,%6,%7}, {%8,%9}, {%0,%1,%2,%3};"
                            : "+f"(acc2[mt][nt][0]), "+f"(acc2[mt][nt][1]),
                              "+f"(acc2[mt][nt][2]), "+f"(acc2[mt][nt][3])
                            : "r"(a[mt][0]), "r"(a[mt][1]), "r"(a[mt][2]), "r"(a[mt][3]),
                              "r"(b[nt][0]), "r"(b[nt][1]));
                    }
            }
        }
        __syncthreads();   // y reads done; AY free

        // ---- write next A tile from registers ----
        if (hasNext) {
#pragma unroll
            for (int j = 0; j < 8; j++) {
                int i2 = tid + 256 * j;
                int r = i2 >> 4, c = i2 & 15;
                *(uint4*)(sm + AYO + r * 272 + c * 16) = pf[j];
            }
        }

        // ---- epilogue: global h16 or fused pool ----
        if (doPool) {
#pragma unroll
            for (int mt = 0; mt < 4; mt++) {
                int ra = row0 + wm * 64 + mt * 16 + g;
                int sgA = g_off[batch[ra]] + sgb[ra];
                int sgB = g_off[batch[ra + 8]] + sgb[ra + 8];
#pragma unroll
                for (int nt = 0; nt < 4; nt++) {
                    int col = wn * 32 + nt * 8 + tg * 2;
                    float2 bv = *(const float2*)(b2 + col);
                    float2 o0 = {acc2[mt][nt][0] + bv.x, acc2[mt][nt][1] + bv.y};
                    float2 o1 = {acc2[mt][nt][2] + bv.x, acc2[mt][nt][3] + bv.y};
                    red_add_v2(out + (size_t)sgA * DD + col, o0);
                    red_add_v2(out + (size_t)sgB * DD + col, o1);
                }
            }
        } else {
#pragma unroll
            for (int mt = 0; mt < 4; mt++) {
#pragma unroll
                for (int nt = 0; nt < 4; nt++) {
                    int col = wn * 32 + nt * 8 + tg * 2;
                    float2 bv = *(const float2*)(b2 + col);
                    int r0 = row0 + wm * 64 + mt * 16 + g;
                    float2 o0, o1;
                    o0.x = acc2[mt][nt][0] + bv.x;
                    o0.y = acc2[mt][nt][1] + bv.y;
                    o1.x = acc2[mt][nt][2] + bv.x;
                    o1.y = acc2[mt][nt][3] + bv.y;
                    if (doRelu2) {
                        o0.x = fmaxf(o0.x, 0.0f); o0.y = fmaxf(o0.y, 0.0f);
                        o1.x = fmaxf(o1.x, 0.0f); o1.y = fmaxf(o1.y, 0.0f);
                    }
                    __half2 p0 = __floats2half2_rn(o0.x, o0.y);
                    __half2 p1 = __floats2half2_rn(o1.x, o1.y);
                    *(__half2*)(H16 + (size_t)r0 * DD + col)       = p0;
                    *(__half2*)(H16 + (size_t)(r0 + 8) * DD + col) = p1;
                }
            }
        }
        __syncthreads();   // STS of next A visible before next GEMM1
    }
}

// ---------------- pooling helpers ---------------------------------------------
__global__ void count_kernel(const int* __restrict__ batch,
                             const int* __restrict__ sgb, int Nn) {
    int i = blockIdx.x * blockDim.x + threadIdx.x;
    if (i < Nn) atomicAdd(&g_cnt[g_off[batch[i]] + sgb[i]], 1.0f);
}

__global__ void div_kernel(float* __restrict__ sums, int total) {
    int i = blockIdx.x * blockDim.x + threadIdx.x;
    if (i >= total) return;
    sums[i] /= fmaxf(g_cnt[i / DD], 1.0f);
}

// ---------------- launch ------------------------------------------------------
extern "C" void kernel_launch(void* const* d_in, const int* in_sizes, int n_in,
                              void* d_out, int out_size) {
    const float* x     = (const float*)d_in[0];
    const int*   edge  = (const int*)d_in[1];
    const int*   batch = (const int*)d_in[2];
    const int*   sgb   = (const int*)d_in[3];
    const int*   nsg   = (const int*)d_in[4];
    const float* W1  = (const float*)d_in[5];
    const float* b1  = (const float*)d_in[6];
    const float* W2  = (const float*)d_in[7];
    const float* b2  = (const float*)d_in[8];
    const float* eps = (const float*)d_in[9];
    float* out = (float*)d_out;

    int N = in_sizes[0] / DD;
    int E = in_sizes[1] / 2;
    int G = in_sizes[4];
    const int* src = edge;
    const int* dst = edge + E;

    void *pa, *pw;
    cudaGetSymbolAddress(&pa, g_agg16);
    cudaGetSymbolAddress(&pw, g_w16t);
    void *ph16;
    cudaGetSymbolAddress(&ph16, g_hh16);
    __half* h16   = (__half*)ph16;
    __half* agg16 = (__half*)pa;
    __half* w16t  = (__half*)pw;

    static bool attrSet = false;
    if (!attrSet) {
        cudaFuncSetAttribute(mlp_fused,
                             cudaFuncAttributeMaxDynamicSharedMemorySize, SMEM_TOT);
        attrSet = true;
    }

    int zb = (out_size + 255) / 256;               // zero blocks
    int setupGrid = 17281 + zb;

    // launch 0: all independent setup concurrently
    setup_kernel<<<setupGrid, 256>>>(dst, E, x, N * DD / 4,
                                     W1, W2, nsg, G, out, out_size);
    scan1_kernel<<<NCHUNK, 256>>>();               // launch 1
    scan23_kernel<<<NCHUNK, 256>>>(E);             // launch 2
    fill_kernel<<<(E + 255) / 256, 256>>>(src, dst, E);  // launch 3

    int ntiles = N / 128;
    int grid = 148 < ntiles ? 148 : ntiles;

    for (int l = 0; l < LL; l++) {
        gather_kernel<<<(int)(((long long)N * 32 + 255) / 256), 256>>>(eps, l, N);
        mlp_fused<<<grid, 256, SMEM_TOT>>>(
            agg16, w16t + (size_t)l * 65536, b1 + (size_t)l * 256,
            w16t + (size_t)l * 65536 + 32768, b2 + (size_t)l * 128,
            h16, batch, sgb, out, ntiles,
            (l < LL - 1) ? 1 : 0, (l == LL - 1) ? 1 : 0);
    }

    count_kernel<<<(N + 255) / 256, 256>>>(batch, sgb, N);
    div_kernel<<<(out_size + 255) / 256, 256>>>(out, out_size);
}

// round 11
// speedup vs baseline: 1.0338x; 1.0144x over previous
#include <cuda_runtime.h>
#include <cuda_fp16.h>
#include <cstdint>
#include <cstddef>

#define NN  102400
#define EE  819200
#define DD  128
#define LL  5
#define TSG 1024
#define NCHUNK 400          // NN / 256

// ---------------- scratch (static device globals) ----------------------------
__device__ __half g_hh16[(size_t)NN * DD];       // fp16 activations (gather in)
__device__ __half g_agg16[(size_t)NN * DD];      // MLP input
__device__ __half g_w16t[(size_t)LL * 65536];    // transposed fp16 weights
__device__ int    g_rowptr[NN + 1];
__device__ int    g_cur[NN];                     // invariant: ==0 at call entry/exit
__device__ int    g_bsum[NCHUNK];
__device__ int    g_col[EE];
__device__ float  g_cnt[TSG];
__device__ int    g_off[64];

// ---------------- mega setup: hist | x2h | convw | prefix | zero --------------
__global__ void setup_kernel(const int* __restrict__ dst, int E,
                             const float* __restrict__ x, int total4,
                             const float* __restrict__ W1,
                             const float* __restrict__ W2,
                             const int* __restrict__ nsg, int G,
                             float* __restrict__ out, int n_out) {
    int b = blockIdx.x, t = threadIdx.x;
    if (b < 3200) {
        int e = b * 256 + t;
        if (e < E) atomicAdd(&g_cur[dst[e]], 1);
    } else if (b < 16000) {
        int i = (b - 3200) * 256 + t;
        if (i < total4) {
            float4 v = ((const float4*)x)[i];
            __half2 h0 = __floats2half2_rn(v.x, v.y);
            __half2 h1 = __floats2half2_rn(v.z, v.w);
            uint2 o = {*(uint32_t*)&h0, *(uint32_t*)&h1};
            ((uint2*)g_hh16)[i] = o;
        }
    } else if (b < 17280) {
        int i = (b - 16000) * 256 + t;
        int l = i >> 16, r = i & 65535;
        float v;
        if (r < 32768) {
            int n = r >> 7, k = r & 127;
            v = W1[(size_t)l * 32768 + k * 256 + n];
        } else {
            int r2 = r - 32768;
            int n = r2 >> 8, k = r2 & 255;
            v = W2[(size_t)l * 32768 + k * 128 + n];
        }
        g_w16t[i] = __float2half_rn(v);
    } else if (b == 17280) {
        if (t == 0) {
            int a = 0;
            for (int g = 0; g < G; ++g) { g_off[g] = a; a += nsg[g]; }
        }
    } else {
        int i = (b - 17281) * 256 + t;
        if (i < n_out) out[i] = 0.0f;
        if (i < TSG) g_cnt[i] = 0.0f;
    }
}

// ---------------- CSR build ----------------------------------------------------
__global__ void scan1_kernel() {
    __shared__ int s[256];
    int t = threadIdx.x, i = blockIdx.x * 256 + t;
    int v = g_cur[i];
    s[t] = v;
    __syncthreads();
#pragma unroll
    for (int o = 1; o < 256; o <<= 1) {
        int u = (t >= o) ? s[t - o] : 0;
        __syncthreads();
        s[t] += u;
        __syncthreads();
    }
    g_rowptr[i] = s[t] - v;
    if (t == 255) g_bsum[blockIdx.x] = s[255];
}

__global__ void scan23_kernel(int E) {
    __shared__ int s[256];
    int b = blockIdx.x, t = threadIdx.x;
    int partial = 0;
    for (int j = t; j < b; j += 256) partial += g_bsum[j];
    s[t] = partial;
    __syncthreads();
#pragma unroll
    for (int o = 128; o > 0; o >>= 1) {
        if (t < o) s[t] += s[t + o];
        __syncthreads();
    }
    int off = s[0];
    g_rowptr[b * 256 + t] += off;
    if (b == 0 && t == 0) g_rowptr[NN] = E;
}

// self-restoring fill with 4-edge ILP: drains g_cur back to 0.
__global__ void fill_kernel(const int* __restrict__ src,
                            const int* __restrict__ dst, int E) {
    int base = (blockIdx.x * blockDim.x + threadIdx.x) * 4;
#pragma unroll
    for (int j = 0; j < 4; j++) {
        int e = base + j;
        if (e < E) {
            int d = dst[e];
            int p = g_rowptr[d] + atomicSub(&g_cur[d], 1) - 1;
            g_col[p] = src[e];
        }
    }
}

// ---------------- gather: agg16[d] = fp16((1+eps)h[d] + sum h[nb]) ------------
__device__ __forceinline__ void acc4(float* acc, uint2 v) {
    float2 f0 = __half22float2(*(const __half2*)&v.x);
    float2 f1 = __half22float2(*(const __half2*)&v.y);
    acc[0] += f0.x; acc[1] += f0.y; acc[2] += f1.x; acc[3] += f1.y;
}

__global__ void gather_kernel(const float* __restrict__ eps, int l, int Nn) {
    long long tid = (long long)blockIdx.x * blockDim.x + threadIdx.x;
    int node = (int)(tid >> 5);
    if (node >= Nn) return;
    int lane = (int)(tid & 31);
    float e1 = 1.0f + eps[l];
    const uint2* hv = (const uint2*)g_hh16;

    float acc[4];
    {
        uint2 v = hv[(size_t)node * 32 + lane];
        float2 f0 = __half22float2(*(const __half2*)&v.x);
        float2 f1 = __half22float2(*(const __half2*)&v.y);
        acc[0] = e1 * f0.x; acc[1] = e1 * f0.y;
        acc[2] = e1 * f1.x; acc[3] = e1 * f1.y;
    }

    int i = g_rowptr[node], t = g_rowptr[node + 1];
    for (; i + 4 <= t; i += 4) {
        int n0 = g_col[i], n1 = g_col[i + 1];
        int n2 = g_col[i + 2], n3 = g_col[i + 3];
        uint2 v0 = hv[(size_t)n0 * 32 + lane];
        uint2 v1 = hv[(size_t)n1 * 32 + lane];
        uint2 v2 = hv[(size_t)n2 * 32 + lane];
        uint2 v3 = hv[(size_t)n3 * 32 + lane];
        acc4(acc, v0); acc4(acc, v1); acc4(acc, v2); acc4(acc, v3);
    }
    for (; i < t; i++) acc4(acc, hv[(size_t)g_col[i] * 32 + lane]);

    __half2 h0 = __floats2half2_rn(acc[0], acc[1]);
    __half2 h1 = __floats2half2_rn(acc[2], acc[3]);
    uint2 o = {*(uint32_t*)&h0, *(uint32_t*)&h1};
    ((uint2*)(g_agg16 + (size_t)node * DD))[lane] = o;
}

// ---------------- persistent fused MLP, register-resident y -------------------
// Warp w owns rows [16w, 16w+16). GEMM1 y kept in registers (C->A frag reuse).
// SMEM: W1 (256 x 272B) | W2 (128 x 528B) | A (128 x 272B)
#define CP16(smb, g) \
    asm volatile("cp.async.cg.shared.global [%0], [%1], 16;" :: "r"(smb), "l"(g))
#define W1O 0
#define W2O 69632
#define AO  137216
#define SMEM_TOT 172032

#define LDX4(r0, r1, r2, r3, ad) \
    asm volatile("ldmatrix.sync.aligned.m8n8.x4.shared.b16 {%0,%1,%2,%3}, [%4];" \
                 : "=r"(r0), "=r"(r1), "=r"(r2), "=r"(r3) : "r"(ad))
#define MMA16816(c, a, b0, b1) \
    asm volatile("mma.sync.aligned.m16n8k16.row.col.f32.f16.f16.f32 " \
                 "{%0,%1,%2,%3}, {%4,%5,%6,%7}, {%8,%9}, {%0,%1,%2,%3};" \
                 : "+f"((c)[0]), "+f"((c)[1]), "+f"((c)[2]), "+f"((c)[3]) \
                 : "r"((a)[0]), "r"((a)[1]), "r"((a)[2]), "r"((a)[3]), \
                   "r"(b0), "r"(b1))

__device__ __forceinline__ void red_add_v2(float* p, float2 v) {
    asm volatile("red.global.add.v2.f32 [%0], {%1,%2};"
                 :: "l"(p), "f"(v.x), "f"(v.y) : "memory");
}

__global__ __launch_bounds__(256, 1) void mlp_fused(
    const __half* __restrict__ A, const __half* __restrict__ W1t,
    const float* __restrict__ b1, const __half* __restrict__ W2t,
    const float* __restrict__ b2, __half* __restrict__ H16,
    const int* __restrict__ batch, const int* __restrict__ sgb,
    float* __restrict__ out, int ntiles, int doRelu2, int doPool) {
    extern __shared__ char sm[];
    uint32_t sb  = (uint32_t)__cvta_generic_to_shared(sm);
    uint32_t w1b = sb + W1O, w2b = sb + W2O, ab = sb + AO;

    int tid  = threadIdx.x;
    int lane = tid & 31;
    int wid  = tid >> 5;
    int m0   = wid * 16;                 // warp's 16 rows
    int stride = gridDim.x;

    // ---- group 0: W1 + A(tile0); group 1: W2 ----
    for (int i = tid; i < 4096; i += 256) {
        int r = i >> 4, c = i & 15;
        CP16(w1b + r * 272 + c * 16, W1t + (size_t)r * 128 + c * 8);
    }
    {
        int row0 = blockIdx.x * 128;
        for (int i = tid; i < 2048; i += 256) {
            int r = i >> 4, c = i & 15;
            CP16(ab + r * 272 + c * 16, A + (size_t)(row0 + r) * 128 + c * 8);
        }
    }
    asm volatile("cp.async.commit_group;");
    for (int i = tid; i < 4096; i += 256) {
        int r = i >> 5, c = i & 31;
        CP16(w2b + r * 528 + c * 16, W2t + (size_t)r * 256 + c * 8);
    }
    asm volatile("cp.async.commit_group;");
    asm volatile("cp.async.wait_group 1;");
    __syncthreads();

    int g   = lane >> 2;
    int tg  = lane & 3;
    // ldmatrix lane addressing components
    int arow = lane & 15;                 // A-frag row
    int asel = lane >> 4;                 // A-frag k half
    int brow = (lane & 7) + ((lane >> 4) & 1) * 8;   // B x4: n within 16
    int bsel = (lane >> 3) & 1;                      // B k half

    bool firstIter = true;
    for (int tile = blockIdx.x; tile < ntiles; tile += stride) {
        int row0 = tile * 128;
        int nextTile = tile + stride;
        bool hasNext = nextTile < ntiles;

        // ---- prefetch next A tile into registers ----
        uint4 pf[8];
        if (hasNext) {
            const uint4* Ag = (const uint4*)(A + (size_t)nextTile * 128 * 128);
#pragma unroll
            for (int j = 0; j < 8; j++) pf[j] = Ag[tid + 256 * j];
        }

        // ============ GEMM1: y[16,256] = A[16,128] @ W1 (per warp) ============
        float acc1[32][4];
#pragma unroll
        for (int nt = 0; nt < 32; nt++)
#pragma unroll
            for (int j = 0; j < 4; j++) acc1[nt][j] = 0.0f;

#pragma unroll
        for (int kt = 0; kt < 8; kt++) {
            uint32_t a[4];
            uint32_t ad = ab + (m0 + arow) * 272 + kt * 32 + asel * 16;
            LDX4(a[0], a[1], a[2], a[3], ad);
#pragma unroll
            for (int np = 0; np < 16; np++) {
                uint32_t b0, b1, b2, b3;
                uint32_t bd = w1b + (np * 16 + brow) * 272 + kt * 32 + bsel * 16;
                LDX4(b0, b1, b2, b3, bd);
                MMA16816(acc1[2 * np],     a, b0, b1);
                MMA16816(acc1[2 * np + 1], a, b2, b3);
            }
        }
        if (firstIter) {
            asm volatile("cp.async.wait_group 0;");   // W2 resident
            firstIter = false;
        }
        __syncthreads();   // all warps done reading A

        // ---- write next A tile from registers (overlaps GEMM2) ----
        if (hasNext) {
#pragma unroll
            for (int j = 0; j < 8; j++) {
                int i2 = tid + 256 * j;
                int r = i2 >> 4, c = i2 & 15;
                *(uint4*)(sm + AO + r * 272 + c * 16) = pf[j];
            }
        }

        // ---- bias + relu + pack y into A-fragments (registers) ----
        uint32_t yh[16][4];
#pragma unroll
        for (int q = 0; q < 16; q++) {
            int ntA = 2 * q, ntB = 2 * q + 1;
            float2 bvA = *(const float2*)(b1 + ntA * 8 + tg * 2);
            float2 bvB = *(const float2*)(b1 + ntB * 8 + tg * 2);
            float a0 = fmaxf(acc1[ntA][0] + bvA.x, 0.0f);
            float a1 = fmaxf(acc1[ntA][1] + bvA.y, 0.0f);
            float a2 = fmaxf(acc1[ntA][2] + bvA.x, 0.0f);
            float a3 = fmaxf(acc1[ntA][3] + bvA.y, 0.0f);
            float c0 = fmaxf(acc1[ntB][0] + bvB.x, 0.0f);
            float c1 = fmaxf(acc1[ntB][1] + bvB.y, 0.0f);
            float c2 = fmaxf(acc1[ntB][2] + bvB.x, 0.0f);
            float c3 = fmaxf(acc1[ntB][3] + bvB.y, 0.0f);
            __half2 p0 = __floats2half2_rn(a0, a1);
            __half2 p1 = __floats2half2_rn(a2, a3);
            __half2 p2 = __floats2half2_rn(c0, c1);
            __half2 p3 = __floats2half2_rn(c2, c3);
            yh[q][0] = *(uint32_t*)&p0;   // rows g,   k 16q+2tg
            yh[q][1] = *(uint32_t*)&p1;   // rows g+8
            yh[q][2] = *(uint32_t*)&p2;   // rows g,   k 16q+8+2tg
            yh[q][3] = *(uint32_t*)&p3;   // rows g+8
        }

        // ============ GEMM2: h[16,128] = y[16,256] @ W2 (y in regs) ============
        float acc2[16][4];
#pragma unroll
        for (int nt = 0; nt < 16; nt++)
#pragma unroll
            for (int j = 0; j < 4; j++) acc2[nt][j] = 0.0f;

#pragma unroll
        for (int kt = 0; kt < 16; kt++) {
#pragma unroll
            for (int np = 0; np < 8; np++) {
                uint32_t b0, b1x, b2, b3;
                uint32_t bd = w2b + (np * 16 + brow) * 528 + kt * 32 + bsel * 16;
                LDX4(b0, b1x, b2, b3, bd);
                MMA16816(acc2[2 * np],     yh[kt], b0, b1x);
                MMA16816(acc2[2 * np + 1], yh[kt], b2, b3);
            }
        }

        // ---- epilogue ----
        if (doPool) {
            int ra = row0 + m0 + g;
            int sgA = g_off[batch[ra]] + sgb[ra];
            int sgB = g_off[batch[ra + 8]] + sgb[ra + 8];
#pragma unroll
            for (int nt = 0; nt < 16; nt++) {
                int col = nt * 8 + tg * 2;
                float2 bv = *(const float2*)(b2 + col);
                float2 o0 = {acc2[nt][0] + bv.x, acc2[nt][1] + bv.y};
                float2 o1 = {acc2[nt][2] + bv.x, acc2[nt][3] + bv.y};
                red_add_v2(out + (size_t)sgA * DD + col, o0);
                red_add_v2(out + (size_t)sgB * DD + col, o1);
            }
        } else {
            int r0 = row0 + m0 + g;
#pragma unroll
            for (int nt = 0; nt < 16; nt++) {
                int col = nt * 8 + tg * 2;
                float2 bv = *(const float2*)(b2 + col);
                float f0 = acc2[nt][0] + bv.x;
                float f1 = acc2[nt][1] + bv.y;
                float f2 = acc2[nt][2] + bv.x;
                float f3 = acc2[nt][3] + bv.y;
                if (doRelu2) {
                    f0 = fmaxf(f0, 0.0f); f1 = fmaxf(f1, 0.0f);
                    f2 = fmaxf(f2, 0.0f); f3 = fmaxf(f3, 0.0f);
                }
                __half2 p0 = __floats2half2_rn(f0, f1);
                __half2 p1 = __floats2half2_rn(f2, f3);
                *(__half2*)(H16 + (size_t)r0 * DD + col)       = p0;
                *(__half2*)(H16 + (size_t)(r0 + 8) * DD + col) = p1;
            }
        }
        __syncthreads();   // STS of next A visible before next GEMM1
    }
}

// ---------------- pooling helpers ---------------------------------------------
__global__ void count_kernel(const int* __restrict__ batch,
                             const int* __restrict__ sgb, int Nn) {
    int i = blockIdx.x * blockDim.x + threadIdx.x;
    if (i < Nn) atomicAdd(&g_cnt[g_off[batch[i]] + sgb[i]], 1.0f);
}

__global__ void div_kernel(float* __restrict__ sums, int total) {
    int i = blockIdx.x * blockDim.x + threadIdx.x;
    if (i >= total) return;
    sums[i] /= fmaxf(g_cnt[i / DD], 1.0f);
}

// ---------------- launch ------------------------------------------------------
extern "C" void kernel_launch(void* const* d_in, const int* in_sizes, int n_in,
                              void* d_out, int out_size) {
    const float* x     = (const float*)d_in[0];
    const int*   edge  = (const int*)d_in[1];
    const int*   batch = (const int*)d_in[2];
    const int*   sgb   = (const int*)d_in[3];
    const int*   nsg   = (const int*)d_in[4];
    const float* W1  = (const float*)d_in[5];
    const float* b1  = (const float*)d_in[6];
    const float* W2  = (const float*)d_in[7];
    const float* b2  = (const float*)d_in[8];
    const float* eps = (const float*)d_in[9];
    float* out = (float*)d_out;

    int N = in_sizes[0] / DD;
    int E = in_sizes[1] / 2;
    int G = in_sizes[4];
    const int* src = edge;
    const int* dst = edge + E;

    void *pa, *pw, *ph16;
    cudaGetSymbolAddress(&pa, g_agg16);
    cudaGetSymbolAddress(&pw, g_w16t);
    cudaGetSymbolAddress(&ph16, g_hh16);
    __half* h16   = (__half*)ph16;
    __half* agg16 = (__half*)pa;
    __half* w16t  = (__half*)pw;

    static bool attrSet = false;
    if (!attrSet) {
        cudaFuncSetAttribute(mlp_fused,
                             cudaFuncAttributeMaxDynamicSharedMemorySize, SMEM_TOT);
        attrSet = true;
    }

    int zb = (out_size + 255) / 256;
    int setupGrid = 17281 + zb;

    setup_kernel<<<setupGrid, 256>>>(dst, E, x, N * DD / 4,
                                     W1, W2, nsg, G, out, out_size);
    scan1_kernel<<<NCHUNK, 256>>>();
    scan23_kernel<<<NCHUNK, 256>>>(E);
    fill_kernel<<<(E / 4 + 255) / 256, 256>>>(src, dst, E);

    int ntiles = N / 128;
    int grid = 148 < ntiles ? 148 : ntiles;

    for (int l = 0; l < LL; l++) {
        gather_kernel<<<(int)(((long long)N * 32 + 255) / 256), 256>>>(eps, l, N);
        mlp_fused<<<grid, 256, SMEM_TOT>>>(
            agg16, w16t + (size_t)l * 65536, b1 + (size_t)l * 256,
            w16t + (size_t)l * 65536 + 32768, b2 + (size_t)l * 128,
            h16, batch, sgb, out, ntiles,
            (l < LL - 1) ? 1 : 0, (l == LL - 1) ? 1 : 0);
    }

    count_kernel<<<(N + 255) / 256, 256>>>(batch, sgb, N);
    div_kernel<<<(out_size + 255) / 256, 256>>>(out, out_size);
}

// round 12
// speedup vs baseline: 1.0688x; 1.0339x over previous
#include <cuda_runtime.h>
#include <cuda_fp16.h>
#include <cstdint>
#include <cstddef>

#define NN  102400
#define EE  819200
#define DD  128
#define LL  5
#define TSG 1024
#define NCHUNK 400          // NN / 256

// ---------------- scratch (static device globals) ----------------------------
__device__ __half g_hh16[(size_t)NN * DD];       // fp16 activations (gather in)
__device__ __half g_agg16[(size_t)NN * DD];      // MLP input
__device__ __half g_w16t[(size_t)LL * 65536];    // transposed fp16 weights
__device__ int    g_rowptr[NN + 1];
__device__ int    g_cur[NN];                     // invariant: ==0 at call entry/exit
__device__ int    g_bsum[NCHUNK];
__device__ int    g_col[EE];
__device__ float  g_cnt[TSG];
__device__ int    g_off[64];

// ---------------- mega setup: hist | x2h | convw | prefix | zero --------------
__global__ void setup_kernel(const int* __restrict__ dst, int E,
                             const float* __restrict__ x, int total4,
                             const float* __restrict__ W1,
                             const float* __restrict__ W2,
                             const int* __restrict__ nsg, int G,
                             float* __restrict__ out, int n_out) {
    int b = blockIdx.x, t = threadIdx.x;
    if (b < 3200) {
        int e = b * 256 + t;
        if (e < E) atomicAdd(&g_cur[dst[e]], 1);
    } else if (b < 16000) {
        int i = (b - 3200) * 256 + t;
        if (i < total4) {
            float4 v = ((const float4*)x)[i];
            __half2 h0 = __floats2half2_rn(v.x, v.y);
            __half2 h1 = __floats2half2_rn(v.z, v.w);
            uint2 o = {*(uint32_t*)&h0, *(uint32_t*)&h1};
            ((uint2*)g_hh16)[i] = o;
        }
    } else if (b < 17280) {
        int i = (b - 16000) * 256 + t;
        int l = i >> 16, r = i & 65535;
        float v;
        if (r < 32768) {
            int n = r >> 7, k = r & 127;
            v = W1[(size_t)l * 32768 + k * 256 + n];
        } else {
            int r2 = r - 32768;
            int n = r2 >> 8, k = r2 & 255;
            v = W2[(size_t)l * 32768 + k * 128 + n];
        }
        g_w16t[i] = __float2half_rn(v);
    } else if (b == 17280) {
        if (t == 0) {
            int a = 0;
            for (int g = 0; g < G; ++g) { g_off[g] = a; a += nsg[g]; }
        }
    } else {
        int i = (b - 17281) * 256 + t;
        if (i < n_out) out[i] = 0.0f;
        if (i < TSG) g_cnt[i] = 0.0f;
    }
}

// ---------------- CSR build ----------------------------------------------------
__global__ void scan1_kernel() {
    __shared__ int s[256];
    int t = threadIdx.x, i = blockIdx.x * 256 + t;
    int v = g_cur[i];
    s[t] = v;
    __syncthreads();
#pragma unroll
    for (int o = 1; o < 256; o <<= 1) {
        int u = (t >= o) ? s[t - o] : 0;
        __syncthreads();
        s[t] += u;
        __syncthreads();
    }
    g_rowptr[i] = s[t] - v;
    if (t == 255) g_bsum[blockIdx.x] = s[255];
}

__global__ void scan23_kernel(int E) {
    __shared__ int s[256];
    int b = blockIdx.x, t = threadIdx.x;
    int partial = 0;
    for (int j = t; j < b; j += 256) partial += g_bsum[j];
    s[t] = partial;
    __syncthreads();
#pragma unroll
    for (int o = 128; o > 0; o >>= 1) {
        if (t < o) s[t] += s[t + o];
        __syncthreads();
    }
    int off = s[0];
    g_rowptr[b * 256 + t] += off;
    if (b == 0 && t == 0) g_rowptr[NN] = E;
}

// self-restoring fill (scalar, high occupancy) + fused pool-count tail blocks.
__global__ void fillcnt_kernel(const int* __restrict__ src,
                               const int* __restrict__ dst, int E, int fb,
                               const int* __restrict__ batch,
                               const int* __restrict__ sgb, int Nn) {
    int b = blockIdx.x, t = threadIdx.x;
    if (b < fb) {
        int e = b * 256 + t;
        if (e < E) {
            int d = dst[e];
            int p = g_rowptr[d] + atomicSub(&g_cur[d], 1) - 1;
            g_col[p] = src[e];
        }
    } else {
        int i = (b - fb) * 256 + t;
        if (i < Nn) atomicAdd(&g_cnt[g_off[batch[i]] + sgb[i]], 1.0f);
    }
}

// ---------------- gather: 2 nodes/warp, 16 lanes x uint4 ----------------------
__device__ __forceinline__ void acc8(float* acc, uint4 v) {
    const __half2* h = (const __half2*)&v;
#pragma unroll
    for (int j = 0; j < 4; j++) {
        float2 f = __half22float2(h[j]);
        acc[2 * j]     += f.x;
        acc[2 * j + 1] += f.y;
    }
}

__global__ void gather_kernel(const float* __restrict__ eps, int l, int Nn) {
    int gw = (blockIdx.x * blockDim.x + threadIdx.x) >> 5;
    int lane = threadIdx.x & 31;
    int node = gw * 2 + (lane >> 4);
    if (node >= Nn) return;
    int sl = lane & 15;                         // 16B chunk index within row
    float e1 = 1.0f + eps[l];
    const uint4* hv = (const uint4*)g_hh16;     // 16 chunks per row

    float acc[8];
    {
        uint4 v = hv[(size_t)node * 16 + sl];
        const __half2* h = (const __half2*)&v;
#pragma unroll
        for (int j = 0; j < 4; j++) {
            float2 f = __half22float2(h[j]);
            acc[2 * j]     = e1 * f.x;
            acc[2 * j + 1] = e1 * f.y;
        }
    }

    int i = g_rowptr[node], t = g_rowptr[node + 1];
    for (; i + 4 <= t; i += 4) {
        int n0 = g_col[i], n1 = g_col[i + 1];
        int n2 = g_col[i + 2], n3 = g_col[i + 3];
        uint4 v0 = hv[(size_t)n0 * 16 + sl];
        uint4 v1 = hv[(size_t)n1 * 16 + sl];
        uint4 v2 = hv[(size_t)n2 * 16 + sl];
        uint4 v3 = hv[(size_t)n3 * 16 + sl];
        acc8(acc, v0); acc8(acc, v1); acc8(acc, v2); acc8(acc, v3);
    }
    for (; i < t; i++) acc8(acc, hv[(size_t)g_col[i] * 16 + sl]);

    __half2 p0 = __floats2half2_rn(acc[0], acc[1]);
    __half2 p1 = __floats2half2_rn(acc[2], acc[3]);
    __half2 p2 = __floats2half2_rn(acc[4], acc[5]);
    __half2 p3 = __floats2half2_rn(acc[6], acc[7]);
    uint4 o = {*(uint32_t*)&p0, *(uint32_t*)&p1, *(uint32_t*)&p2, *(uint32_t*)&p3};
    ((uint4*)(g_agg16 + (size_t)node * DD))[sl] = o;
}

// ---------------- persistent fused MLP, register-resident y -------------------
// Warp w owns rows [16w, 16w+16). GEMM1 y kept in registers (C->A frag reuse).
// SMEM: W1 (256 x 272B) | W2 (128 x 528B) | A (128 x 272B)
#define CP16(smb, g) \
    asm volatile("cp.async.cg.shared.global [%0], [%1], 16;" :: "r"(smb), "l"(g))
#define W1O 0
#define W2O 69632
#define AO  137216
#define SMEM_TOT 172032

#define LDX4(r0, r1, r2, r3, ad) \
    asm volatile("ldmatrix.sync.aligned.m8n8.x4.shared.b16 {%0,%1,%2,%3}, [%4];" \
                 : "=r"(r0), "=r"(r1), "=r"(r2), "=r"(r3) : "r"(ad))
#define MMA16816(c, a, b0, b1) \
    asm volatile("mma.sync.aligned.m16n8k16.row.col.f32.f16.f16.f32 " \
                 "{%0,%1,%2,%3}, {%4,%5,%6,%7}, {%8,%9}, {%0,%1,%2,%3};" \
                 : "+f"((c)[0]), "+f"((c)[1]), "+f"((c)[2]), "+f"((c)[3]) \
                 : "r"((a)[0]), "r"((a)[1]), "r"((a)[2]), "r"((a)[3]), \
                   "r"(b0), "r"(b1))

__device__ __forceinline__ void red_add_v2(float* p, float2 v) {
    asm volatile("red.global.add.v2.f32 [%0], {%1,%2};"
                 :: "l"(p), "f"(v.x), "f"(v.y) : "memory");
}

__global__ __launch_bounds__(256, 1) void mlp_fused(
    const __half* __restrict__ A, const __half* __restrict__ W1t,
    const float* __restrict__ b1, const __half* __restrict__ W2t,
    const float* __restrict__ b2, __half* __restrict__ H16,
    const int* __restrict__ batch, const int* __restrict__ sgb,
    float* __restrict__ out, int ntiles, int doRelu2, int doPool) {
    extern __shared__ char sm[];
    uint32_t sb  = (uint32_t)__cvta_generic_to_shared(sm);
    uint32_t w1b = sb + W1O, w2b = sb + W2O, ab = sb + AO;

    int tid  = threadIdx.x;
    int lane = tid & 31;
    int wid  = tid >> 5;
    int m0   = wid * 16;                 // warp's 16 rows
    int stride = gridDim.x;

    // ---- group 0: W1 + A(tile0); group 1: W2 ----
    for (int i = tid; i < 4096; i += 256) {
        int r = i >> 4, c = i & 15;
        CP16(w1b + r * 272 + c * 16, W1t + (size_t)r * 128 + c * 8);
    }
    {
        int row0 = blockIdx.x * 128;
        for (int i = tid; i < 2048; i += 256) {
            int r = i >> 4, c = i & 15;
            CP16(ab + r * 272 + c * 16, A + (size_t)(row0 + r) * 128 + c * 8);
        }
    }
    asm volatile("cp.async.commit_group;");
    for (int i = tid; i < 4096; i += 256) {
        int r = i >> 5, c = i & 31;
        CP16(w2b + r * 528 + c * 16, W2t + (size_t)r * 256 + c * 8);
    }
    asm volatile("cp.async.commit_group;");
    asm volatile("cp.async.wait_group 1;");
    __syncthreads();

    int g   = lane >> 2;
    int tg  = lane & 3;
    int arow = lane & 15;
    int asel = lane >> 4;
    int brow = (lane & 7) + ((lane >> 4) & 1) * 8;
    int bsel = (lane >> 3) & 1;

    bool firstIter = true;
    for (int tile = blockIdx.x; tile < ntiles; tile += stride) {
        int row0 = tile * 128;
        int nextTile = tile + stride;
        bool hasNext = nextTile < ntiles;

        // ---- prefetch next A tile into registers ----
        uint4 pf[8];
        if (hasNext) {
            const uint4* Ag = (const uint4*)(A + (size_t)nextTile * 128 * 128);
#pragma unroll
            for (int j = 0; j < 8; j++) pf[j] = Ag[tid + 256 * j];
        }

        // ============ GEMM1: y[16,256] = A[16,128] @ W1 (per warp) ============
        float acc1[32][4];
#pragma unroll
        for (int nt = 0; nt < 32; nt++)
#pragma unroll
            for (int j = 0; j < 4; j++) acc1[nt][j] = 0.0f;

#pragma unroll
        for (int kt = 0; kt < 8; kt++) {
            uint32_t a[4];
            uint32_t ad = ab + (m0 + arow) * 272 + kt * 32 + asel * 16;
            LDX4(a[0], a[1], a[2], a[3], ad);
#pragma unroll
            for (int np = 0; np < 16; np++) {
                uint32_t b0, b1, b2, b3;
                uint32_t bd = w1b + (np * 16 + brow) * 272 + kt * 32 + bsel * 16;
                LDX4(b0, b1, b2, b3, bd);
                MMA16816(acc1[2 * np],     a, b0, b1);
                MMA16816(acc1[2 * np + 1], a, b2, b3);
            }
        }
        if (firstIter) {
            asm volatile("cp.async.wait_group 0;");   // W2 resident
            firstIter = false;
        }
        __syncthreads();   // all warps done reading A

        // ---- write next A tile from registers (overlaps GEMM2) ----
        if (hasNext) {
#pragma unroll
            for (int j = 0; j < 8; j++) {
                int i2 = tid + 256 * j;
                int r = i2 >> 4, c = i2 & 15;
                *(uint4*)(sm + AO + r * 272 + c * 16) = pf[j];
            }
        }

        // ---- bias + relu + pack y into A-fragments (registers) ----
        uint32_t yh[16][4];
#pragma unroll
        for (int q = 0; q < 16; q++) {
            int ntA = 2 * q, ntB = 2 * q + 1;
            float2 bvA = *(const float2*)(b1 + ntA * 8 + tg * 2);
            float2 bvB = *(const float2*)(b1 + ntB * 8 + tg * 2);
            float a0 = fmaxf(acc1[ntA][0] + bvA.x, 0.0f);
            float a1 = fmaxf(acc1[ntA][1] + bvA.y, 0.0f);
            float a2 = fmaxf(acc1[ntA][2] + bvA.x, 0.0f);
            float a3 = fmaxf(acc1[ntA][3] + bvA.y, 0.0f);
            float c0 = fmaxf(acc1[ntB][0] + bvB.x, 0.0f);
            float c1 = fmaxf(acc1[ntB][1] + bvB.y, 0.0f);
            float c2 = fmaxf(acc1[ntB][2] + bvB.x, 0.0f);
            float c3 = fmaxf(acc1[ntB][3] + bvB.y, 0.0f);
            __half2 p0 = __floats2half2_rn(a0, a1);
            __half2 p1 = __floats2half2_rn(a2, a3);
            __half2 p2 = __floats2half2_rn(c0, c1);
            __half2 p3 = __floats2half2_rn(c2, c3);
            yh[q][0] = *(uint32_t*)&p0;
            yh[q][1] = *(uint32_t*)&p1;
            yh[q][2] = *(uint32_t*)&p2;
            yh[q][3] = *(uint32_t*)&p3;
        }

        // ============ GEMM2: h[16,128] = y[16,256] @ W2 (y in regs) ============
        float acc2[16][4];
#pragma unroll
        for (int nt = 0; nt < 16; nt++)
#pragma unroll
            for (int j = 0; j < 4; j++) acc2[nt][j] = 0.0f;

#pragma unroll
        for (int kt = 0; kt < 16; kt++) {
#pragma unroll
            for (int np = 0; np < 8; np++) {
                uint32_t b0, b1x, b2, b3;
                uint32_t bd = w2b + (np * 16 + brow) * 528 + kt * 32 + bsel * 16;
                LDX4(b0, b1x, b2, b3, bd);
                MMA16816(acc2[2 * np],     yh[kt], b0, b1x);
                MMA16816(acc2[2 * np + 1], yh[kt], b2, b3);
            }
        }

        // ---- epilogue ----
        if (doPool) {
            int ra = row0 + m0 + g;
            int sgA = g_off[batch[ra]] + sgb[ra];
            int sgB = g_off[batch[ra + 8]] + sgb[ra + 8];
#pragma unroll
            for (int nt = 0; nt < 16; nt++) {
                int col = nt * 8 + tg * 2;
                float2 bv = *(const float2*)(b2 + col);
                float2 o0 = {acc2[nt][0] + bv.x, acc2[nt][1] + bv.y};
                float2 o1 = {acc2[nt][2] + bv.x, acc2[nt][3] + bv.y};
                red_add_v2(out + (size_t)sgA * DD + col, o0);
                red_add_v2(out + (size_t)sgB * DD + col, o1);
            }
        } else {
            int r0 = row0 + m0 + g;
#pragma unroll
            for (int nt = 0; nt < 16; nt++) {
                int col = nt * 8 + tg * 2;
                float2 bv = *(const float2*)(b2 + col);
                float f0 = acc2[nt][0] + bv.x;
                float f1 = acc2[nt][1] + bv.y;
                float f2 = acc2[nt][2] + bv.x;
                float f3 = acc2[nt][3] + bv.y;
                if (doRelu2) {
                    f0 = fmaxf(f0, 0.0f); f1 = fmaxf(f1, 0.0f);
                    f2 = fmaxf(f2, 0.0f); f3 = fmaxf(f3, 0.0f);
                }
                __half2 p0 = __floats2half2_rn(f0, f1);
                __half2 p1 = __floats2half2_rn(f2, f3);
                *(__half2*)(H16 + (size_t)r0 * DD + col)       = p0;
                *(__half2*)(H16 + (size_t)(r0 + 8) * DD + col) = p1;
            }
        }
        __syncthreads();   // STS of next A visible before next GEMM1
    }
}

// ---------------- div ---------------------------------------------------------
__global__ void div_kernel(float* __restrict__ sums, int total) {
    int i = blockIdx.x * blockDim.x + threadIdx.x;
    if (i >= total) return;
    sums[i] /= fmaxf(g_cnt[i / DD], 1.0f);
}

// ---------------- launch ------------------------------------------------------
extern "C" void kernel_launch(void* const* d_in, const int* in_sizes, int n_in,
                              void* d_out, int out_size) {
    const float* x     = (const float*)d_in[0];
    const int*   edge  = (const int*)d_in[1];
    const int*   batch = (const int*)d_in[2];
    const int*   sgb   = (const int*)d_in[3];
    const int*   nsg   = (const int*)d_in[4];
    const float* W1  = (const float*)d_in[5];
    const float* b1  = (const float*)d_in[6];
    const float* W2  = (const float*)d_in[7];
    const float* b2  = (const float*)d_in[8];
    const float* eps = (const float*)d_in[9];
    float* out = (float*)d_out;

    int N = in_sizes[0] / DD;
    int E = in_sizes[1] / 2;
    int G = in_sizes[4];
    const int* src = edge;
    const int* dst = edge + E;

    void *pa, *pw, *ph16;
    cudaGetSymbolAddress(&pa, g_agg16);
    cudaGetSymbolAddress(&pw, g_w16t);
    cudaGetSymbolAddress(&ph16, g_hh16);
    __half* h16   = (__half*)ph16;
    __half* agg16 = (__half*)pa;
    __half* w16t  = (__half*)pw;

    static bool attrSet = false;
    if (!attrSet) {
        cudaFuncSetAttribute(mlp_fused,
                             cudaFuncAttributeMaxDynamicSharedMemorySize, SMEM_TOT);
        attrSet = true;
    }

    int zb = (out_size + 255) / 256;
    int setupGrid = 17281 + zb;

    setup_kernel<<<setupGrid, 256>>>(dst, E, x, N * DD / 4,
                                     W1, W2, nsg, G, out, out_size);
    scan1_kernel<<<NCHUNK, 256>>>();
    scan23_kernel<<<NCHUNK, 256>>>(E);

    int fb = (E + 255) / 256;
    int cb = (N + 255) / 256;
    fillcnt_kernel<<<fb + cb, 256>>>(src, dst, E, fb, batch, sgb, N);

    int ntiles = N / 128;
    int grid = 148 < ntiles ? 148 : ntiles;
    int gatherBlocks = (int)(((long long)(N + 1) / 2 * 32 + 255) / 256);

    for (int l = 0; l < LL; l++) {
        gather_kernel<<<gatherBlocks, 256>>>(eps, l, N);
        mlp_fused<<<grid, 256, SMEM_TOT>>>(
            agg16, w16t + (size_t)l * 65536, b1 + (size_t)l * 256,
            w16t + (size_t)l * 65536 + 32768, b2 + (size_t)l * 128,
            h16, batch, sgb, out, ntiles,
            (l < LL - 1) ? 1 : 0, (l == LL - 1) ? 1 : 0);
    }

    div_kernel<<<(out_size + 255) / 256, 256>>>(out, out_size);
}

// round 13
// speedup vs baseline: 1.0753x; 1.0060x over previous
#include <cuda_runtime.h>
#include <cuda_fp16.h>
#include <cstdint>
#include <cstddef>

#define NN  102400
#define EE  819200
#define DD  128
#define LL  5
#define TSG 1024
#define NCHUNK 400          // NN / 256

// ---------------- scratch (static device globals) ----------------------------
__device__ __half g_hh16[(size_t)NN * DD];       // fp16 activations (gather in)
__device__ __half g_agg16[(size_t)NN * DD];      // MLP input
__device__ __half g_w16t[(size_t)LL * 65536];    // transposed fp16 weights
__device__ int    g_rowptr[NN + 1];
__device__ int    g_cur[NN];                     // invariant: ==0 at call entry/exit
__device__ int    g_bsum[NCHUNK];
__device__ int    g_col[EE];
__device__ float  g_cnt[TSG];
__device__ int    g_off[64];

// ---------------- mega setup: hist | x2h | convw | prefix | zero --------------
__global__ void setup_kernel(const int* __restrict__ dst, int E,
                             const float* __restrict__ x, int total4,
                             const float* __restrict__ W1,
                             const float* __restrict__ W2,
                             const int* __restrict__ nsg, int G,
                             float* __restrict__ out, int n_out) {
    int b = blockIdx.x, t = threadIdx.x;
    if (b < 3200) {
        int e = b * 256 + t;
        if (e < E) atomicAdd(&g_cur[dst[e]], 1);
    } else if (b < 16000) {
        int i = (b - 3200) * 256 + t;
        if (i < total4) {
            float4 v = ((const float4*)x)[i];
            __half2 h0 = __floats2half2_rn(v.x, v.y);
            __half2 h1 = __floats2half2_rn(v.z, v.w);
            uint2 o = {*(uint32_t*)&h0, *(uint32_t*)&h1};
            ((uint2*)g_hh16)[i] = o;
        }
    } else if (b < 17280) {
        int i = (b - 16000) * 256 + t;
        int l = i >> 16, r = i & 65535;
        float v;
        if (r < 32768) {
            int n = r >> 7, k = r & 127;
            v = W1[(size_t)l * 32768 + k * 256 + n];
        } else {
            int r2 = r - 32768;
            int n = r2 >> 8, k = r2 & 255;
            v = W2[(size_t)l * 32768 + k * 128 + n];
        }
        g_w16t[i] = __float2half_rn(v);
    } else if (b == 17280) {
        if (t == 0) {
            int a = 0;
            for (int g = 0; g < G; ++g) { g_off[g] = a; a += nsg[g]; }
        }
    } else {
        int i = (b - 17281) * 256 + t;
        if (i < n_out) out[i] = 0.0f;
        if (i < TSG) g_cnt[i] = 0.0f;
    }
}

// ---------------- CSR build + pool-count --------------------------------------
// blocks [0, NCHUNK): per-block scan of degrees; [NCHUNK, NCHUNK+cb): pool count
__global__ void scan1cnt_kernel(const int* __restrict__ batch,
                                const int* __restrict__ sgb, int Nn) {
    int b = blockIdx.x, t = threadIdx.x;
    if (b < NCHUNK) {
        __shared__ int s[256];
        int i = b * 256 + t;
        int v = g_cur[i];
        s[t] = v;
        __syncthreads();
#pragma unroll
        for (int o = 1; o < 256; o <<= 1) {
            int u = (t >= o) ? s[t - o] : 0;
            __syncthreads();
            s[t] += u;
            __syncthreads();
        }
        g_rowptr[i] = s[t] - v;
        if (t == 255) g_bsum[b] = s[255];
    } else {
        int i = (b - NCHUNK) * 256 + t;
        if (i < Nn) atomicAdd(&g_cnt[g_off[batch[i]] + sgb[i]], 1.0f);
    }
}

__global__ void scan23_kernel(int E) {
    __shared__ int s[256];
    int b = blockIdx.x, t = threadIdx.x;
    int partial = 0;
    for (int j = t; j < b; j += 256) partial += g_bsum[j];
    s[t] = partial;
    __syncthreads();
#pragma unroll
    for (int o = 128; o > 0; o >>= 1) {
        if (t < o) s[t] += s[t + o];
        __syncthreads();
    }
    int off = s[0];
    g_rowptr[b * 256 + t] += off;
    if (b == 0 && t == 0) g_rowptr[NN] = E;
}

// self-restoring fill (scalar, high occupancy): drains g_cur back to 0.
__global__ void fill_kernel(const int* __restrict__ src,
                            const int* __restrict__ dst, int E) {
    int e = blockIdx.x * blockDim.x + threadIdx.x;
    if (e >= E) return;
    int d = dst[e];
    int p = g_rowptr[d] + atomicSub(&g_cur[d], 1) - 1;
    g_col[p] = src[e];
}

// ---------------- gather: 2 nodes/warp, 16 lanes x uint4, unroll 8 ------------
__device__ __forceinline__ void acc8(float* acc, uint4 v) {
    const __half2* h = (const __half2*)&v;
#pragma unroll
    for (int j = 0; j < 4; j++) {
        float2 f = __half22float2(h[j]);
        acc[2 * j]     += f.x;
        acc[2 * j + 1] += f.y;
    }
}

__global__ void gather_kernel(const float* __restrict__ eps, int l, int Nn) {
    int gw = (blockIdx.x * blockDim.x + threadIdx.x) >> 5;
    int lane = threadIdx.x & 31;
    int node = gw * 2 + (lane >> 4);
    if (node >= Nn) return;
    int sl = lane & 15;                         // 16B chunk index within row
    float e1 = 1.0f + eps[l];
    const uint4* hv = (const uint4*)g_hh16;     // 16 chunks per row

    float acc[8];
    {
        uint4 v = hv[(size_t)node * 16 + sl];
        const __half2* h = (const __half2*)&v;
#pragma unroll
        for (int j = 0; j < 4; j++) {
            float2 f = __half22float2(h[j]);
            acc[2 * j]     = e1 * f.x;
            acc[2 * j + 1] = e1 * f.y;
        }
    }

    int i = g_rowptr[node], t = g_rowptr[node + 1];
    for (; i + 8 <= t; i += 8) {
        int n[8];
#pragma unroll
        for (int j = 0; j < 8; j++) n[j] = g_col[i + j];
        uint4 v[8];
#pragma unroll
        for (int j = 0; j < 8; j++) v[j] = hv[(size_t)n[j] * 16 + sl];
#pragma unroll
        for (int j = 0; j < 8; j++) acc8(acc, v[j]);
    }
    if (i + 4 <= t) {
        int n0 = g_col[i], n1 = g_col[i + 1];
        int n2 = g_col[i + 2], n3 = g_col[i + 3];
        uint4 v0 = hv[(size_t)n0 * 16 + sl];
        uint4 v1 = hv[(size_t)n1 * 16 + sl];
        uint4 v2 = hv[(size_t)n2 * 16 + sl];
        uint4 v3 = hv[(size_t)n3 * 16 + sl];
        acc8(acc, v0); acc8(acc, v1); acc8(acc, v2); acc8(acc, v3);
        i += 4;
    }
    for (; i < t; i++) acc8(acc, hv[(size_t)g_col[i] * 16 + sl]);

    __half2 p0 = __floats2half2_rn(acc[0], acc[1]);
    __half2 p1 = __floats2half2_rn(acc[2], acc[3]);
    __half2 p2 = __floats2half2_rn(acc[4], acc[5]);
    __half2 p3 = __floats2half2_rn(acc[6], acc[7]);
    uint4 o = {*(uint32_t*)&p0, *(uint32_t*)&p1, *(uint32_t*)&p2, *(uint32_t*)&p3};
    ((uint4*)(g_agg16 + (size_t)node * DD))[sl] = o;
}

// ---------------- persistent fused MLP, register-resident y -------------------
// Warp w owns rows [16w, 16w+16). GEMM1 y kept in registers (C->A frag reuse).
// SMEM: W1 (256 x 272B) | W2 (128 x 528B) | A (128 x 272B)
#define CP16(smb, g) \
    asm volatile("cp.async.cg.shared.global [%0], [%1], 16;" :: "r"(smb), "l"(g))
#define W1O 0
#define W2O 69632
#define AO  137216
#define SMEM_TOT 172032

#define LDX4(r0, r1, r2, r3, ad) \
    asm volatile("ldmatrix.sync.aligned.m8n8.x4.shared.b16 {%0,%1,%2,%3}, [%4];" \
                 : "=r"(r0), "=r"(r1), "=r"(r2), "=r"(r3) : "r"(ad))
#define MMA16816(c, a, b0, b1) \
    asm volatile("mma.sync.aligned.m16n8k16.row.col.f32.f16.f16.f32 " \
                 "{%0,%1,%2,%3}, {%4,%5,%6,%7}, {%8,%9}, {%0,%1,%2,%3};" \
                 : "+f"((c)[0]), "+f"((c)[1]), "+f"((c)[2]), "+f"((c)[3]) \
                 : "r"((a)[0]), "r"((a)[1]), "r"((a)[2]), "r"((a)[3]), \
                   "r"(b0), "r"(b1))

__device__ __forceinline__ void red_add_v2(float* p, float2 v) {
    asm volatile("red.global.add.v2.f32 [%0], {%1,%2};"
                 :: "l"(p), "f"(v.x), "f"(v.y) : "memory");
}

__global__ __launch_bounds__(256, 1) void mlp_fused(
    const __half* __restrict__ A, const __half* __restrict__ W1t,
    const float* __restrict__ b1, const __half* __restrict__ W2t,
    const float* __restrict__ b2, __half* __restrict__ H16,
    const int* __restrict__ batch, const int* __restrict__ sgb,
    float* __restrict__ out, int ntiles, int doRelu2, int doPool) {
    extern __shared__ char sm[];
    uint32_t sb  = (uint32_t)__cvta_generic_to_shared(sm);
    uint32_t w1b = sb + W1O, w2b = sb + W2O, ab = sb + AO;

    int tid  = threadIdx.x;
    int lane = tid & 31;
    int wid  = tid >> 5;
    int m0   = wid * 16;                 // warp's 16 rows
    int stride = gridDim.x;

    // ---- group 0: W1 + A(tile0); group 1: W2 ----
    for (int i = tid; i < 4096; i += 256) {
        int r = i >> 4, c = i & 15;
        CP16(w1b + r * 272 + c * 16, W1t + (size_t)r * 128 + c * 8);
    }
    {
        int row0 = blockIdx.x * 128;
        for (int i = tid; i < 2048; i += 256) {
            int r = i >> 4, c = i & 15;
            CP16(ab + r * 272 + c * 16, A + (size_t)(row0 + r) * 128 + c * 8);
        }
    }
    asm volatile("cp.async.commit_group;");
    for (int i = tid; i < 4096; i += 256) {
        int r = i >> 5, c = i & 31;
        CP16(w2b + r * 528 + c * 16, W2t + (size_t)r * 256 + c * 8);
    }
    asm volatile("cp.async.commit_group;");
    asm volatile("cp.async.wait_group 1;");
    __syncthreads();

    int g   = lane >> 2;
    int tg  = lane & 3;
    int arow = lane & 15;
    int asel = lane >> 4;
    int brow = (lane & 7) + ((lane >> 4) & 1) * 8;
    int bsel = (lane >> 3) & 1;

    bool firstIter = true;
    for (int tile = blockIdx.x; tile < ntiles; tile += stride) {
        int row0 = tile * 128;
        int nextTile = tile + stride;
        bool hasNext = nextTile < ntiles;

        // ---- prefetch next A tile into registers ----
        uint4 pf[8];
        if (hasNext) {
            const uint4* Ag = (const uint4*)(A + (size_t)nextTile * 128 * 128);
#pragma unroll
            for (int j = 0; j < 8; j++) pf[j] = Ag[tid + 256 * j];
        }

        // ============ GEMM1: y[16,256] = A[16,128] @ W1 (per warp) ============
        float acc1[32][4];
#pragma unroll
        for (int nt = 0; nt < 32; nt++)
#pragma unroll
            for (int j = 0; j < 4; j++) acc1[nt][j] = 0.0f;

#pragma unroll
        for (int kt = 0; kt < 8; kt++) {
            uint32_t a[4];
            uint32_t ad = ab + (m0 + arow) * 272 + kt * 32 + asel * 16;
            LDX4(a[0], a[1], a[2], a[3], ad);
#pragma unroll
            for (int np = 0; np < 16; np++) {
                uint32_t b0, b1, b2, b3;
                uint32_t bd = w1b + (np * 16 + brow) * 272 + kt * 32 + bsel * 16;
                LDX4(b0, b1, b2, b3, bd);
                MMA16816(acc1[2 * np],     a, b0, b1);
                MMA16816(acc1[2 * np + 1], a, b2, b3);
            }
        }
        if (firstIter) {
            asm volatile("cp.async.wait_group 0;");   // W2 resident
            firstIter = false;
        }
        __syncthreads();   // all warps done reading A

        // ---- write next A tile from registers (overlaps GEMM2) ----
        if (hasNext) {
#pragma unroll
            for (int j = 0; j < 8; j++) {
                int i2 = tid + 256 * j;
                int r = i2 >> 4, c = i2 & 15;
                *(uint4*)(sm + AO + r * 272 + c * 16) = pf[j];
            }
        }

        // ---- bias + relu + pack y into A-fragments (registers) ----
        uint32_t yh[16][4];
#pragma unroll
        for (int q = 0; q < 16; q++) {
            int ntA = 2 * q, ntB = 2 * q + 1;
            float2 bvA = *(const float2*)(b1 + ntA * 8 + tg * 2);
            float2 bvB = *(const float2*)(b1 + ntB * 8 + tg * 2);
            float a0 = fmaxf(acc1[ntA][0] + bvA.x, 0.0f);
            float a1 = fmaxf(acc1[ntA][1] + bvA.y, 0.0f);
            float a2 = fmaxf(acc1[ntA][2] + bvA.x, 0.0f);
            float a3 = fmaxf(acc1[ntA][3] + bvA.y, 0.0f);
            float c0 = fmaxf(acc1[ntB][0] + bvB.x, 0.0f);
            float c1 = fmaxf(acc1[ntB][1] + bvB.y, 0.0f);
            float c2 = fmaxf(acc1[ntB][2] + bvB.x, 0.0f);
            float c3 = fmaxf(acc1[ntB][3] + bvB.y, 0.0f);
            __half2 p0 = __floats2half2_rn(a0, a1);
            __half2 p1 = __floats2half2_rn(a2, a3);
            __half2 p2 = __floats2half2_rn(c0, c1);
            __half2 p3 = __floats2half2_rn(c2, c3);
            yh[q][0] = *(uint32_t*)&p0;
            yh[q][1] = *(uint32_t*)&p1;
            yh[q][2] = *(uint32_t*)&p2;
            yh[q][3] = *(uint32_t*)&p3;
        }

        // ============ GEMM2: h[16,128] = y[16,256] @ W2 (y in regs) ============
        float acc2[16][4];
#pragma unroll
        for (int nt = 0; nt < 16; nt++)
#pragma unroll
            for (int j = 0; j < 4; j++) acc2[nt][j] = 0.0f;

#pragma unroll
        for (int kt = 0; kt < 16; kt++) {
#pragma unroll
            for (int np = 0; np < 8; np++) {
                uint32_t b0, b1x, b2, b3;
                uint32_t bd = w2b + (np * 16 + brow) * 528 + kt * 32 + bsel * 16;
                LDX4(b0, b1x, b2, b3, bd);
                MMA16816(acc2[2 * np],     yh[kt], b0, b1x);
                MMA16816(acc2[2 * np + 1], yh[kt], b2, b3);
            }
        }

        // ---- epilogue ----
        if (doPool) {
            int ra = row0 + m0 + g;
            int sgA = g_off[batch[ra]] + sgb[ra];
            int sgB = g_off[batch[ra + 8]] + sgb[ra + 8];
#pragma unroll
            for (int nt = 0; nt < 16; nt++) {
                int col = nt * 8 + tg * 2;
                float2 bv = *(const float2*)(b2 + col);
                float2 o0 = {acc2[nt][0] + bv.x, acc2[nt][1] + bv.y};
                float2 o1 = {acc2[nt][2] + bv.x, acc2[nt][3] + bv.y};
                red_add_v2(out + (size_t)sgA * DD + col, o0);
                red_add_v2(out + (size_t)sgB * DD + col, o1);
            }
        } else {
            int r0 = row0 + m0 + g;
#pragma unroll
            for (int nt = 0; nt < 16; nt++) {
                int col = nt * 8 + tg * 2;
                float2 bv = *(const float2*)(b2 + col);
                float f0 = acc2[nt][0] + bv.x;
                float f1 = acc2[nt][1] + bv.y;
                float f2 = acc2[nt][2] + bv.x;
                float f3 = acc2[nt][3] + bv.y;
                if (doRelu2) {
                    f0 = fmaxf(f0, 0.0f); f1 = fmaxf(f1, 0.0f);
                    f2 = fmaxf(f2, 0.0f); f3 = fmaxf(f3, 0.0f);
                }
                __half2 p0 = __floats2half2_rn(f0, f1);
                __half2 p1 = __floats2half2_rn(f2, f3);
                *(__half2*)(H16 + (size_t)r0 * DD + col)       = p0;
                *(__half2*)(H16 + (size_t)(r0 + 8) * DD + col) = p1;
            }
        }
        __syncthreads();   // STS of next A visible before next GEMM1
    }
}

// ---------------- div ---------------------------------------------------------
__global__ void div_kernel(float* __restrict__ sums, int total) {
    int i = blockIdx.x * blockDim.x + threadIdx.x;
    if (i >= total) return;
    sums[i] /= fmaxf(g_cnt[i / DD], 1.0f);
}

// ---------------- launch ------------------------------------------------------
extern "C" void kernel_launch(void* const* d_in, const int* in_sizes, int n_in,
                              void* d_out, int out_size) {
    const float* x     = (const float*)d_in[0];
    const int*   edge  = (const int*)d_in[1];
    const int*   batch = (const int*)d_in[2];
    const int*   sgb   = (const int*)d_in[3];
    const int*   nsg   = (const int*)d_in[4];
    const float* W1  = (const float*)d_in[5];
    const float* b1  = (const float*)d_in[6];
    const float* W2  = (const float*)d_in[7];
    const float* b2  = (const float*)d_in[8];
    const float* eps = (const float*)d_in[9];
    float* out = (float*)d_out;

    int N = in_sizes[0] / DD;
    int E = in_sizes[1] / 2;
    int G = in_sizes[4];
    const int* src = edge;
    const int* dst = edge + E;

    void *pa, *pw, *ph16;
    cudaGetSymbolAddress(&pa, g_agg16);
    cudaGetSymbolAddress(&pw, g_w16t);
    cudaGetSymbolAddress(&ph16, g_hh16);
    __half* h16   = (__half*)ph16;
    __half* agg16 = (__half*)pa;
    __half* w16t  = (__half*)pw;

    static bool attrSet = false;
    if (!attrSet) {
        cudaFuncSetAttribute(mlp_fused,
                             cudaFuncAttributeMaxDynamicSharedMemorySize, SMEM_TOT);
        attrSet = true;
    }

    int zb = (out_size + 255) / 256;
    int setupGrid = 17281 + zb;
    int cb = (N + 255) / 256;

    setup_kernel<<<setupGrid, 256>>>(dst, E, x, N * DD / 4,
                                     W1, W2, nsg, G, out, out_size);
    scan1cnt_kernel<<<NCHUNK + cb, 256>>>(batch, sgb, N);
    scan23_kernel<<<NCHUNK, 256>>>(E);
    fill_kernel<<<(E + 255) / 256, 256>>>(src, dst, E);

    int ntiles = N / 128;
    int grid = 148 < ntiles ? 148 : ntiles;
    int gatherBlocks = (int)(((long long)(N + 1) / 2 * 32 + 255) / 256);

    for (int l = 0; l < LL; l++) {
        gather_kernel<<<gatherBlocks, 256>>>(eps, l, N);
        mlp_fused<<<grid, 256, SMEM_TOT>>>(
            agg16, w16t + (size_t)l * 65536, b1 + (size_t)l * 256,
            w16t + (size_t)l * 65536 + 32768, b2 + (size_t)l * 128,
            h16, batch, sgb, out, ntiles,
            (l < LL - 1) ? 1 : 0, (l == LL - 1) ? 1 : 0);
    }

    div_kernel<<<(out_size + 255) / 256, 256>>>(out, out_size);
}

// round 14
// speedup vs baseline: 1.0773x; 1.0019x over previous
#include <cuda_runtime.h>
#include <cuda_fp16.h>
#include <cstdint>
#include <cstddef>

#define NN  102400
#define EE  819200
#define DD  128
#define LL  5
#define TSG 1024
#define NCHUNK 400          // NN / 256

// ---------------- scratch (static device globals) ----------------------------
__device__ __half g_hh16[(size_t)NN * DD];       // fp16 activations (gather in)
__device__ __half g_agg16[(size_t)NN * DD];      // MLP input
__device__ __half g_w16t[(size_t)LL * 65536];    // transposed fp16 weights
__device__ int    g_rowptr[NN + 1];
__device__ int    g_cur[NN];                     // invariant: ==0 at call entry/exit
__device__ int    g_bsum[NCHUNK];
__device__ int    g_col[EE];
__device__ float  g_cnt[TSG];
__device__ int    g_off[64];

// ---------------- mega setup: hist | x2h | convw | prefix | zero --------------
__global__ void setup_kernel(const int* __restrict__ dst, int E,
                             const float* __restrict__ x, int total4,
                             const float* __restrict__ W1,
                             const float* __restrict__ W2,
                             const int* __restrict__ nsg, int G,
                             float* __restrict__ out, int n_out) {
    int b = blockIdx.x, t = threadIdx.x;
    if (b < 3200) {
        int e = b * 256 + t;
        if (e < E) atomicAdd(&g_cur[dst[e]], 1);
    } else if (b < 16000) {
        int i = (b - 3200) * 256 + t;
        if (i < total4) {
            float4 v = ((const float4*)x)[i];
            __half2 h0 = __floats2half2_rn(v.x, v.y);
            __half2 h1 = __floats2half2_rn(v.z, v.w);
            uint2 o = {*(uint32_t*)&h0, *(uint32_t*)&h1};
            ((uint2*)g_hh16)[i] = o;
        }
    } else if (b < 17280) {
        int i = (b - 16000) * 256 + t;
        int l = i >> 16, r = i & 65535;
        float v;
        if (r < 32768) {
            int n = r >> 7, k = r & 127;
            v = W1[(size_t)l * 32768 + k * 256 + n];
        } else {
            int r2 = r - 32768;
            int n = r2 >> 8, k = r2 & 255;
            v = W2[(size_t)l * 32768 + k * 128 + n];
        }
        g_w16t[i] = __float2half_rn(v);
    } else if (b == 17280) {
        if (t == 0) {
            int a = 0;
            for (int g = 0; g < G; ++g) { g_off[g] = a; a += nsg[g]; }
        }
    } else {
        int i = (b - 17281) * 256 + t;
        if (i < n_out) out[i] = 0.0f;
        if (i < TSG) g_cnt[i] = 0.0f;
    }
}

// ---------------- CSR build + pool-count --------------------------------------
__global__ void scan1cnt_kernel(const int* __restrict__ batch,
                                const int* __restrict__ sgb, int Nn) {
    int b = blockIdx.x, t = threadIdx.x;
    if (b < NCHUNK) {
        __shared__ int s[256];
        int i = b * 256 + t;
        int v = g_cur[i];
        s[t] = v;
        __syncthreads();
#pragma unroll
        for (int o = 1; o < 256; o <<= 1) {
            int u = (t >= o) ? s[t - o] : 0;
            __syncthreads();
            s[t] += u;
            __syncthreads();
        }
        g_rowptr[i] = s[t] - v;
        if (t == 255) g_bsum[b] = s[255];
    } else {
        int i = (b - NCHUNK) * 256 + t;
        if (i < Nn) atomicAdd(&g_cnt[g_off[batch[i]] + sgb[i]], 1.0f);
    }
}

__global__ void scan23_kernel(int E) {
    __shared__ int s[256];
    int b = blockIdx.x, t = threadIdx.x;
    int partial = 0;
    for (int j = t; j < b; j += 256) partial += g_bsum[j];
    s[t] = partial;
    __syncthreads();
#pragma unroll
    for (int o = 128; o > 0; o >>= 1) {
        if (t < o) s[t] += s[t + o];
        __syncthreads();
    }
    int off = s[0];
    g_rowptr[b * 256 + t] += off;
    if (b == 0 && t == 0) g_rowptr[NN] = E;
}

// self-restoring fill (scalar, high occupancy): drains g_cur back to 0.
__global__ void fill_kernel(const int* __restrict__ src,
                            const int* __restrict__ dst, int E) {
    int e = blockIdx.x * blockDim.x + threadIdx.x;
    if (e >= E) return;
    int d = dst[e];
    int p = g_rowptr[d] + atomicSub(&g_cur[d], 1) - 1;
    g_col[p] = src[e];
}

// ---------------- gather over node range [nodeBeg, nodeEnd) -------------------
__device__ __forceinline__ void acc8(float* acc, uint4 v) {
    const __half2* h = (const __half2*)&v;
#pragma unroll
    for (int j = 0; j < 4; j++) {
        float2 f = __half22float2(h[j]);
        acc[2 * j]     += f.x;
        acc[2 * j + 1] += f.y;
    }
}

__global__ void gather_kernel(const float* __restrict__ eps, int l,
                              int nodeBeg, int nodeEnd) {
    int gw = (blockIdx.x * blockDim.x + threadIdx.x) >> 5;
    int lane = threadIdx.x & 31;
    int node = nodeBeg + gw * 2 + (lane >> 4);
    if (node >= nodeEnd) return;
    int sl = lane & 15;
    float e1 = 1.0f + eps[l];
    const uint4* hv = (const uint4*)g_hh16;

    float acc[8];
    {
        uint4 v = hv[(size_t)node * 16 + sl];
        const __half2* h = (const __half2*)&v;
#pragma unroll
        for (int j = 0; j < 4; j++) {
            float2 f = __half22float2(h[j]);
            acc[2 * j]     = e1 * f.x;
            acc[2 * j + 1] = e1 * f.y;
        }
    }

    int i = g_rowptr[node], t = g_rowptr[node + 1];
    for (; i + 8 <= t; i += 8) {
        int n[8];
#pragma unroll
        for (int j = 0; j < 8; j++) n[j] = g_col[i + j];
        uint4 v[8];
#pragma unroll
        for (int j = 0; j < 8; j++) v[j] = hv[(size_t)n[j] * 16 + sl];
#pragma unroll
        for (int j = 0; j < 8; j++) acc8(acc, v[j]);
    }
    if (i + 4 <= t) {
        int n0 = g_col[i], n1 = g_col[i + 1];
        int n2 = g_col[i + 2], n3 = g_col[i + 3];
        uint4 v0 = hv[(size_t)n0 * 16 + sl];
        uint4 v1 = hv[(size_t)n1 * 16 + sl];
        uint4 v2 = hv[(size_t)n2 * 16 + sl];
        uint4 v3 = hv[(size_t)n3 * 16 + sl];
        acc8(acc, v0); acc8(acc, v1); acc8(acc, v2); acc8(acc, v3);
        i += 4;
    }
    for (; i < t; i++) acc8(acc, hv[(size_t)g_col[i] * 16 + sl]);

    __half2 p0 = __floats2half2_rn(acc[0], acc[1]);
    __half2 p1 = __floats2half2_rn(acc[2], acc[3]);
    __half2 p2 = __floats2half2_rn(acc[4], acc[5]);
    __half2 p3 = __floats2half2_rn(acc[6], acc[7]);
    uint4 o = {*(uint32_t*)&p0, *(uint32_t*)&p1, *(uint32_t*)&p2, *(uint32_t*)&p3};
    ((uint4*)(g_agg16 + (size_t)node * DD))[sl] = o;
}

// ---------------- persistent fused MLP over tile range ------------------------
#define CP16(smb, g) \
    asm volatile("cp.async.cg.shared.global [%0], [%1], 16;" :: "r"(smb), "l"(g))
#define W1O 0
#define W2O 69632
#define AO  137216
#define SMEM_TOT 172032

#define LDX4(r0, r1, r2, r3, ad) \
    asm volatile("ldmatrix.sync.aligned.m8n8.x4.shared.b16 {%0,%1,%2,%3}, [%4];" \
                 : "=r"(r0), "=r"(r1), "=r"(r2), "=r"(r3) : "r"(ad))
#define MMA16816(c, a, b0, b1) \
    asm volatile("mma.sync.aligned.m16n8k16.row.col.f32.f16.f16.f32 " \
                 "{%0,%1,%2,%3}, {%4,%5,%6,%7}, {%8,%9}, {%0,%1,%2,%3};" \
                 : "+f"((c)[0]), "+f"((c)[1]), "+f"((c)[2]), "+f"((c)[3]) \
                 : "r"((a)[0]), "r"((a)[1]), "r"((a)[2]), "r"((a)[3]), \
                   "r"(b0), "r"(b1))

__device__ __forceinline__ void red_add_v2(float* p, float2 v) {
    asm volatile("red.global.add.v2.f32 [%0], {%1,%2};"
                 :: "l"(p), "f"(v.x), "f"(v.y) : "memory");
}

__global__ __launch_bounds__(256, 1) void mlp_fused(
    const __half* __restrict__ A, const __half* __restrict__ W1t,
    const float* __restrict__ b1, const __half* __restrict__ W2t,
    const float* __restrict__ b2, __half* __restrict__ H16,
    const int* __restrict__ batch, const int* __restrict__ sgb,
    float* __restrict__ out, int tileBeg, int tileEnd,
    int doRelu2, int doPool) {
    extern __shared__ char sm[];
    uint32_t sb  = (uint32_t)__cvta_generic_to_shared(sm);
    uint32_t w1b = sb + W1O, w2b = sb + W2O, ab = sb + AO;

    int tid  = threadIdx.x;
    int lane = tid & 31;
    int wid  = tid >> 5;
    int m0   = wid * 16;
    int stride = gridDim.x;

    // ---- group 0: W1 + A(first tile); group 1: W2 ----
    for (int i = tid; i < 4096; i += 256) {
        int r = i >> 4, c = i & 15;
        CP16(w1b + r * 272 + c * 16, W1t + (size_t)r * 128 + c * 8);
    }
    {
        int row0 = (tileBeg + blockIdx.x) * 128;
        for (int i = tid; i < 2048; i += 256) {
            int r = i >> 4, c = i & 15;
            CP16(ab + r * 272 + c * 16, A + (size_t)(row0 + r) * 128 + c * 8);
        }
    }
    asm volatile("cp.async.commit_group;");
    for (int i = tid; i < 4096; i += 256) {
        int r = i >> 5, c = i & 31;
        CP16(w2b + r * 528 + c * 16, W2t + (size_t)r * 256 + c * 8);
    }
    asm volatile("cp.async.commit_group;");
    asm volatile("cp.async.wait_group 1;");
    __syncthreads();

    int g   = lane >> 2;
    int tg  = lane & 3;
    int arow = lane & 15;
    int asel = lane >> 4;
    int brow = (lane & 7) + ((lane >> 4) & 1) * 8;
    int bsel = (lane >> 3) & 1;

    bool firstIter = true;
    for (int tile = tileBeg + blockIdx.x; tile < tileEnd; tile += stride) {
        int row0 = tile * 128;
        int nextTile = tile + stride;
        bool hasNext = nextTile < tileEnd;

        uint4 pf[8];
        if (hasNext) {
            const uint4* Ag = (const uint4*)(A + (size_t)nextTile * 128 * 128);
#pragma unroll
            for (int j = 0; j < 8; j++) pf[j] = Ag[tid + 256 * j];
        }

        // ============ GEMM1: y[16,256] = A[16,128] @ W1 (per warp) ============
        float acc1[32][4];
#pragma unroll
        for (int nt = 0; nt < 32; nt++)
#pragma unroll
            for (int j = 0; j < 4; j++) acc1[nt][j] = 0.0f;

#pragma unroll
        for (int kt = 0; kt < 8; kt++) {
            uint32_t a[4];
            uint32_t ad = ab + (m0 + arow) * 272 + kt * 32 + asel * 16;
            LDX4(a[0], a[1], a[2], a[3], ad);
#pragma unroll
            for (int np = 0; np < 16; np++) {
                uint32_t b0, b1, b2, b3;
                uint32_t bd = w1b + (np * 16 + brow) * 272 + kt * 32 + bsel * 16;
                LDX4(b0, b1, b2, b3, bd);
                MMA16816(acc1[2 * np],     a, b0, b1);
                MMA16816(acc1[2 * np + 1], a, b2, b3);
            }
        }
        if (firstIter) {
            asm volatile("cp.async.wait_group 0;");
            firstIter = false;
        }
        __syncthreads();

        if (hasNext) {
#pragma unroll
            for (int j = 0; j < 8; j++) {
                int i2 = tid + 256 * j;
                int r = i2 >> 4, c = i2 & 15;
                *(uint4*)(sm + AO + r * 272 + c * 16) = pf[j];
            }
        }

        // ---- bias + relu + pack y into A-fragments (registers) ----
        uint32_t yh[16][4];
#pragma unroll
        for (int q = 0; q < 16; q++) {
            int ntA = 2 * q, ntB = 2 * q + 1;
            float2 bvA = *(const float2*)(b1 + ntA * 8 + tg * 2);
            float2 bvB = *(const float2*)(b1 + ntB * 8 + tg * 2);
            float a0 = fmaxf(acc1[ntA][0] + bvA.x, 0.0f);
            float a1 = fmaxf(acc1[ntA][1] + bvA.y, 0.0f);
            float a2 = fmaxf(acc1[ntA][2] + bvA.x, 0.0f);
            float a3 = fmaxf(acc1[ntA][3] + bvA.y, 0.0f);
            float c0 = fmaxf(acc1[ntB][0] + bvB.x, 0.0f);
            float c1 = fmaxf(acc1[ntB][1] + bvB.y, 0.0f);
            float c2 = fmaxf(acc1[ntB][2] + bvB.x, 0.0f);
            float c3 = fmaxf(acc1[ntB][3] + bvB.y, 0.0f);
            __half2 p0 = __floats2half2_rn(a0, a1);
            __half2 p1 = __floats2half2_rn(a2, a3);
            __half2 p2 = __floats2half2_rn(c0, c1);
            __half2 p3 = __floats2half2_rn(c2, c3);
            yh[q][0] = *(uint32_t*)&p0;
            yh[q][1] = *(uint32_t*)&p1;
            yh[q][2] = *(uint32_t*)&p2;
            yh[q][3] = *(uint32_t*)&p3;
        }

        // ============ GEMM2: h[16,128] = y[16,256] @ W2 (y in regs) ============
        float acc2[16][4];
#pragma unroll
        for (int nt = 0; nt < 16; nt++)
#pragma unroll
            for (int j = 0; j < 4; j++) acc2[nt][j] = 0.0f;

#pragma unroll
        for (int kt = 0; kt < 16; kt++) {
#pragma unroll
            for (int np = 0; np < 8; np++) {
                uint32_t b0, b1x, b2, b3;
                uint32_t bd = w2b + (np * 16 + brow) * 528 + kt * 32 + bsel * 16;
                LDX4(b0, b1x, b2, b3, bd);
                MMA16816(acc2[2 * np],     yh[kt], b0, b1x);
                MMA16816(acc2[2 * np + 1], yh[kt], b2, b3);
            }
        }

        // ---- epilogue ----
        if (doPool) {
            int ra = row0 + m0 + g;
            int sgA = g_off[batch[ra]] + sgb[ra];
            int sgB = g_off[batch[ra + 8]] + sgb[ra + 8];
#pragma unroll
            for (int nt = 0; nt < 16; nt++) {
                int col = nt * 8 + tg * 2;
                float2 bv = *(const float2*)(b2 + col);
                float2 o0 = {acc2[nt][0] + bv.x, acc2[nt][1] + bv.y};
                float2 o1 = {acc2[nt][2] + bv.x, acc2[nt][3] + bv.y};
                red_add_v2(out + (size_t)sgA * DD + col, o0);
                red_add_v2(out + (size_t)sgB * DD + col, o1);
            }
        } else {
            int r0 = row0 + m0 + g;
#pragma unroll
            for (int nt = 0; nt < 16; nt++) {
                int col = nt * 8 + tg * 2;
                float2 bv = *(const float2*)(b2 + col);
                float f0 = acc2[nt][0] + bv.x;
                float f1 = acc2[nt][1] + bv.y;
                float f2 = acc2[nt][2] + bv.x;
                float f3 = acc2[nt][3] + bv.y;
                if (doRelu2) {
                    f0 = fmaxf(f0, 0.0f); f1 = fmaxf(f1, 0.0f);
                    f2 = fmaxf(f2, 0.0f); f3 = fmaxf(f3, 0.0f);
                }
                __half2 p0 = __floats2half2_rn(f0, f1);
                __half2 p1 = __floats2half2_rn(f2, f3);
                *(__half2*)(H16 + (size_t)r0 * DD + col)       = p0;
                *(__half2*)(H16 + (size_t)(r0 + 8) * DD + col) = p1;
            }
        }
        __syncthreads();
    }
}

// ---------------- div ---------------------------------------------------------
__global__ void div_kernel(float* __restrict__ sums, int total) {
    int i = blockIdx.x * blockDim.x + threadIdx.x;
    if (i >= total) return;
    sums[i] /= fmaxf(g_cnt[i / DD], 1.0f);
}

// ---------------- launch ------------------------------------------------------
extern "C" void kernel_launch(void* const* d_in, const int* in_sizes, int n_in,
                              void* d_out, int out_size) {
    const float* x     = (const float*)d_in[0];
    const int*   edge  = (const int*)d_in[1];
    const int*   batch = (const int*)d_in[2];
    const int*   sgb   = (const int*)d_in[3];
    const int*   nsg   = (const int*)d_in[4];
    const float* W1  = (const float*)d_in[5];
    const float* b1  = (const float*)d_in[6];
    const float* W2  = (const float*)d_in[7];
    const float* b2  = (const float*)d_in[8];
    const float* eps = (const float*)d_in[9];
    float* out = (float*)d_out;

    int N = in_sizes[0] / DD;
    int E = in_sizes[1] / 2;
    int G = in_sizes[4];
    const int* src = edge;
    const int* dst = edge + E;

    void *pa, *pw, *ph16;
    cudaGetSymbolAddress(&pa, g_agg16);
    cudaGetSymbolAddress(&pw, g_w16t);
    cudaGetSymbolAddress(&ph16, g_hh16);
    __half* h16   = (__half*)ph16;
    __half* agg16 = (__half*)pa;
    __half* w16t  = (__half*)pw;

    static cudaStream_t s2 = nullptr;
    static cudaEvent_t evF[LL], evJ[LL];
    static bool inited = false;
    if (!inited) {
        cudaFuncSetAttribute(mlp_fused,
                             cudaFuncAttributeMaxDynamicSharedMemorySize, SMEM_TOT);
        cudaStreamCreateWithFlags(&s2, cudaStreamNonBlocking);
        for (int l = 0; l < LL; l++) {
            cudaEventCreateWithFlags(&evF[l], cudaEventDisableTiming);
            cudaEventCreateWithFlags(&evJ[l], cudaEventDisableTiming);
        }
        inited = true;
    }

    int zb = (out_size + 255) / 256;
    int setupGrid = 17281 + zb;
    int cb = (N + 255) / 256;

    setup_kernel<<<setupGrid, 256>>>(dst, E, x, N * DD / 4,
                                     W1, W2, nsg, G, out, out_size);
    scan1cnt_kernel<<<NCHUNK + cb, 256>>>(batch, sgb, N);
    scan23_kernel<<<NCHUNK, 256>>>(E);
    fill_kernel<<<(E + 255) / 256, 256>>>(src, dst, E);

    int ntiles = N / 128;                 // 800
    int halfTiles = ntiles / 2;           // 400
    int nHalf = N / 2;
    int gb = ((nHalf + 1) / 2 * 32 + 255) / 256;   // blocks per gather half
    int mg = 74 < halfTiles ? 74 : halfTiles;

    for (int l = 0; l < LL; l++) {
        int relu2 = (l < LL - 1) ? 1 : 0;
        int pool  = (l == LL - 1) ? 1 : 0;
        const __half* w1l = w16t + (size_t)l * 65536;
        const __half* w2l = w16t + (size_t)l * 65536 + 32768;
        const float*  b1l = b1 + (size_t)l * 256;
        const float*  b2l = b2 + (size_t)l * 128;

        cudaEventRecord(evF[l], 0);
        cudaStreamWaitEvent(s2, evF[l], 0);

        gather_kernel<<<gb, 256, 0, 0>>>(eps, l, 0, nHalf);
        gather_kernel<<<gb, 256, 0, s2>>>(eps, l, nHalf, N);

        mlp_fused<<<mg, 256, SMEM_TOT, 0>>>(
            agg16, w1l, b1l, w2l, b2l, h16, batch, sgb, out,
            0, halfTiles, relu2, pool);
        mlp_fused<<<mg, 256, SMEM_TOT, s2>>>(
            agg16, w1l, b1l, w2l, b2l, h16, batch, sgb, out,
            halfTiles, ntiles, relu2, pool);

        cudaEventRecord(evJ[l], s2);
        cudaStreamWaitEvent(0, evJ[l], 0);
    }

    div_kernel<<<(out_size + 255) / 256, 256>>>(out, out_size);
}